// round 9
// baseline (speedup 1.0000x reference)
#include <cuda_runtime.h>
#include <cuda_fp16.h>
#include <cstdint>

#define NB 16
#define DD 256
#define LL 2048
#define KK 8192
#define NN (NB*LL)        // 32768 z vectors
#define NTOT (NB*DD*LL)
#define BM 256
#define BN 128            // 96 tensor + 32 SIMT codes per tile
#define BKH 64            // k halves per stage
#define NKITER (DD/BKH)   // 4
#define HSTRIDE 72        // padded halves per row (conflict-free)
#define A_HALFS (BM*HSTRIDE)
#define B_HALFS (BN*HSTRIDE)
#define STAGE_HALFS (A_HALFS+B_HALFS)
#define STAGE_BYTES (STAGE_HALFS*2)       // 55296
#define NSTAGE 3
#define DYNSMEM (NSTAGE*STAGE_BYTES)      // 165888
#define NGRP 256
#define RESCUE_MARGIN 2.5e-4f
#define EZ_UNSCALE (-0.000244140625f)     // -2 * 2^-13 (exact)
#define NTHREADS 384

// ---------------- device scratch ----------------
__device__ __align__(1024) __half g_zH[(size_t)NN*DD];  // fp16 z   [n][d]
__device__ __align__(1024) __half g_cH[(size_t)KK*DD];  // fp16 cb*8192 [k][d]
__device__ unsigned long long g_grp[(size_t)NN*NGRP];   // per-group packed minima
__device__ float  g_z2[NN];
__device__ float  g_e2[KK];
__device__ int    g_idx[NN];
__device__ double g_loss;

// ---------------- helpers ----------------
__device__ __forceinline__ uint32_t smem_u32(const void* p) {
    uint32_t a;
    asm("{ .reg .u64 t; cvta.to.shared.u64 t, %1; cvt.u32.u64 %0, t; }" : "=r"(a) : "l"(p));
    return a;
}
#define CP_ASYNC16(sa, gp) \
    asm volatile("cp.async.cg.shared.global [%0], [%1], 16;" :: "r"(sa), "l"(gp) : "memory")
#define CP_COMMIT() asm volatile("cp.async.commit_group;" ::: "memory")
#define CP_WAIT1()  asm volatile("cp.async.wait_group 1;" ::: "memory")
#define CP_WAIT0()  asm volatile("cp.async.wait_group 0;" ::: "memory")

__device__ __forceinline__ void mma_f16(float* c, const uint32_t* a, const uint32_t* b) {
    asm volatile(
        "mma.sync.aligned.m16n8k16.row.col.f32.f16.f16.f32 "
        "{%0,%1,%2,%3}, {%4,%5,%6,%7}, {%8,%9}, {%0,%1,%2,%3};"
        : "+f"(c[0]), "+f"(c[1]), "+f"(c[2]), "+f"(c[3])
        : "r"(a[0]), "r"(a[1]), "r"(a[2]), "r"(a[3]), "r"(b[0]), "r"(b[1]));
}

// ---------------- prep / small kernels (R2-validated numerics) ----------------
__global__ void reset_kernel() { g_loss = 0.0; }

__global__ void init_grp_kernel() {
    size_t i = (size_t)blockIdx.x * 256 + threadIdx.x;
    ((ulonglong2*)g_grp)[i] = make_ulonglong2(~0ull, ~0ull);
}

__global__ void e2_kernel(const float* __restrict__ cb) {
    int warp = blockIdx.x * 8 + (threadIdx.x >> 5);
    int lane = threadIdx.x & 31;
    const float* r = cb + (size_t)warp * DD;
    float s = 0.f;
#pragma unroll
    for (int i = 0; i < DD / 32; i++) { float v = r[lane + i * 32]; s = fmaf(v, v, s); }
#pragma unroll
    for (int o = 16; o > 0; o >>= 1) s += __shfl_down_sync(0xffffffffu, s, o);
    if (lane == 0) g_e2[warp] = s;
}

__global__ void z2_kernel(const float* __restrict__ z) {
    int n = blockIdx.x * 256 + threadIdx.x;
    int b = n >> 11, l = n & 2047;
    const float* p = z + (size_t)b * (DD * LL) + l;
    float s = 0.f;
#pragma unroll 8
    for (int d = 0; d < DD; d++) {
        float v = p[(size_t)d * LL];
        s = __fadd_rn(s, __fmul_rn(v, v));
    }
    g_z2[n] = s;
}

__global__ void prep_c_kernel(const float* __restrict__ cb) {
    int i = blockIdx.x * 256 + threadIdx.x;       // over KK*DD/4
    float4 v = reinterpret_cast<const float4*>(cb)[i];
    __half2 h0 = __floats2half2_rn(v.x * 8192.f, v.y * 8192.f);
    __half2 h1 = __floats2half2_rn(v.z * 8192.f, v.w * 8192.f);
    reinterpret_cast<__half2*>(g_cH)[i * 2]     = h0;
    reinterpret_cast<__half2*>(g_cH)[i * 2 + 1] = h1;
}

__global__ void prep_z_kernel(const float* __restrict__ z) {
    int gid = blockIdx.x * 256 + threadIdx.x;     // NN*64 threads
    int n  = gid & (NN - 1);
    int d0 = (gid >> 15) << 2;
    int b = n >> 11, l = n & 2047;
    const float* p = z + ((size_t)b * DD + d0) * LL + l;
    float x0 = p[0], x1 = p[LL], x2 = p[2 * LL], x3 = p[3 * LL];
    __half2* o = reinterpret_cast<__half2*>(&g_zH[(size_t)n * DD + d0]);
    o[0] = __floats2half2_rn(x0, x1);
    o[1] = __floats2half2_rn(x2, x3);
}

// ---------------- main GEMM: 8 tensor warps (96 codes) + 4 HFMA2 warps (32 codes) ----------------
__device__ __forceinline__ void stage_load(__half* buf, int m0, int n0, int kk0, int tid) {
#pragma unroll
    for (int it = 0; it < 8; it++) {              // A: 256 rows x 128B
        int idx = tid + it * 256;
        int row = idx >> 3, ch = (idx & 7) << 3;
        uint32_t sa = smem_u32(buf + row * HSTRIDE + ch);
        CP_ASYNC16(sa, &g_zH[(size_t)(m0 + row) * DD + kk0 + ch]);
    }
#pragma unroll
    for (int it = 0; it < 4; it++) {              // B: 128 rows x 128B
        int idx = tid + it * 256;
        int row = idx >> 3, ch = (idx & 7) << 3;
        uint32_t sa = smem_u32(buf + A_HALFS + row * HSTRIDE + ch);
        CP_ASYNC16(sa, &g_cH[(size_t)(n0 + row) * DD + kk0 + ch]);
    }
}

__global__ __launch_bounds__(NTHREADS, 1) void vq_mma_kernel() {
    extern __shared__ __align__(16) __half hsm[];
    const int tid = threadIdx.x;
    const int wid = tid >> 5, lane = tid & 31;
    const int m0 = blockIdx.x * BM;
    const int n0 = blockIdx.y * BN;
    const int gbase = blockIdx.y * 4;

    // tensor-role ids
    const int warpM = (wid >> 1) & 3, warpN = wid & 1;
    const int q = lane >> 2, r = lane & 3;
    // simt-role ids (wid 8..11)
    const int ws = wid - 8;
    const int mg = lane >> 2, ng = lane & 3;
    const int rbase = ws * 64 + mg * 8;

    float c[4][6][4];           // tensor accumulators
    __half2 acc2[8][8];         // SIMT k-parity accumulators
    float   facc[8][8];         // SIMT fp32 flushed totals
    if (wid < 8) {
#pragma unroll
        for (int i = 0; i < 4; i++)
#pragma unroll
            for (int j = 0; j < 6; j++)
#pragma unroll
                for (int t = 0; t < 4; t++) c[i][j][t] = 0.f;
    } else {
#pragma unroll
        for (int i = 0; i < 8; i++)
#pragma unroll
            for (int j = 0; j < 8; j++) {
                acc2[i][j] = __floats2half2_rn(0.f, 0.f);
                facc[i][j] = 0.f;
            }
    }

    if (tid < 256) { stage_load(hsm, m0, n0, 0, tid); }
    CP_COMMIT();
    if (tid < 256) { stage_load(hsm + STAGE_HALFS, m0, n0, BKH, tid); }
    CP_COMMIT();

    for (int i = 0; i < NKITER; i++) {
        if (i < NKITER - 1) CP_WAIT1(); else CP_WAIT0();
        __syncthreads();
        if (i + 2 < NKITER && tid < 256) {
            stage_load(hsm + ((i + 2) % NSTAGE) * STAGE_HALFS, m0, n0, (i + 2) * BKH, tid);
        }
        if (i + 2 < NKITER) CP_COMMIT();
        const __half* As = hsm + (i % NSTAGE) * STAGE_HALFS;
        const __half* Bs = As + A_HALFS;

        if (wid < 8) {
            // -------- tensor warps: 96 codes --------
#pragma unroll
            for (int kb = 0; kb < BKH; kb += 16) {
                uint32_t a[4][4], b[6][2];
#pragma unroll
                for (int mf = 0; mf < 4; mf++) {
                    int r0 = warpM * 64 + mf * 16 + q;
                    a[mf][0] = *reinterpret_cast<const uint32_t*>(&As[r0 * HSTRIDE + kb + 2 * r]);
                    a[mf][1] = *reinterpret_cast<const uint32_t*>(&As[(r0 + 8) * HSTRIDE + kb + 2 * r]);
                    a[mf][2] = *reinterpret_cast<const uint32_t*>(&As[r0 * HSTRIDE + kb + 2 * r + 8]);
                    a[mf][3] = *reinterpret_cast<const uint32_t*>(&As[(r0 + 8) * HSTRIDE + kb + 2 * r + 8]);
                }
#pragma unroll
                for (int nf = 0; nf < 6; nf++) {
                    int cc = warpN * 48 + nf * 8 + q;
                    b[nf][0] = *reinterpret_cast<const uint32_t*>(&Bs[cc * HSTRIDE + kb + 2 * r]);
                    b[nf][1] = *reinterpret_cast<const uint32_t*>(&Bs[cc * HSTRIDE + kb + 2 * r + 8]);
                }
#pragma unroll
                for (int mf = 0; mf < 4; mf++)
#pragma unroll
                    for (int nf = 0; nf < 6; nf++)
                        mma_f16(c[mf][nf], a[mf], b[nf]);
            }
        } else {
            // -------- SIMT HFMA2 warps: codes 96..127 --------
#pragma unroll 4
            for (int kp = 0; kp < 32; kp++) {
                __half2 av[8], bv[8];
#pragma unroll
                for (int ii = 0; ii < 8; ii++) {
                    int p = (ii + mg) & 7;   // bank stagger
                    av[ii] = *reinterpret_cast<const __half2*>(&As[(rbase + p) * HSTRIDE + 2 * kp]);
                }
#pragma unroll
                for (int jj = 0; jj < 8; jj++) {
                    int t = (jj + 2 * ng) & 7;
                    bv[jj] = *reinterpret_cast<const __half2*>(&Bs[(96 + ng * 8 + t) * HSTRIDE + 2 * kp]);
                }
#pragma unroll
                for (int ii = 0; ii < 8; ii++)
#pragma unroll
                    for (int jj = 0; jj < 8; jj++)
                        acc2[ii][jj] = __hfma2(av[ii], bv[jj], acc2[ii][jj]);
                if ((kp & 15) == 15) {   // flush to fp32 every 32 k
#pragma unroll
                    for (int ii = 0; ii < 8; ii++)
#pragma unroll
                        for (int jj = 0; jj < 8; jj++) {
                            float2 f = __half22float2(acc2[ii][jj]);
                            facc[ii][jj] += f.x + f.y;
                            acc2[ii][jj] = __floats2half2_rn(0.f, 0.f);
                        }
                }
            }
        }
        __syncthreads();
    }

    // ---- epilogue ----
    if (wid < 8) {
        // groups: warpN0 -> gA=0 (nf 0..3), gB=1 (nf 4,5); warpN1 -> gA=1 (nf 0,1), gB=2 (nf 2..5)
        int gA = (warpN == 0) ? 0 : 1;
        int nfSplit = (warpN == 0) ? 4 : 2;
#pragma unroll
        for (int mf = 0; mf < 4; mf++) {
#pragma unroll
            for (int half = 0; half < 2; half++) {
                int lrow = warpM * 64 + mf * 16 + q + half * 8;
                float z2v = g_z2[m0 + lrow];
                unsigned long long bestA = ~0ull, bestB = ~0ull;
#pragma unroll
                for (int nf = 0; nf < 6; nf++) {
                    int k0 = n0 + warpN * 48 + nf * 8 + 2 * r;
                    float e20 = __ldg(&g_e2[k0]);
                    float e21 = __ldg(&g_e2[k0 + 1]);
                    float s0 = __fadd_rn(__fadd_rn(z2v, e20), c[mf][nf][half * 2 + 0] * EZ_UNSCALE);
                    float s1 = __fadd_rn(__fadd_rn(z2v, e21), c[mf][nf][half * 2 + 1] * EZ_UNSCALE);
                    unsigned long long p0 = ((unsigned long long)__float_as_uint(s0) << 32) | (unsigned)k0;
                    unsigned long long p1 = ((unsigned long long)__float_as_uint(s1) << 32) | (unsigned)(k0 + 1);
                    unsigned long long pm = p0 < p1 ? p0 : p1;
                    if (nf < nfSplit) { if (pm < bestA) bestA = pm; }
                    else             { if (pm < bestB) bestB = pm; }
                }
#pragma unroll
                for (int off = 1; off < 4; off <<= 1) {
                    unsigned long long oA = __shfl_xor_sync(0xffffffffu, bestA, off);
                    unsigned long long oB = __shfl_xor_sync(0xffffffffu, bestB, off);
                    if (oA < bestA) bestA = oA;
                    if (oB < bestB) bestB = oB;
                }
                if (r == 0) {
                    atomicMin(&g_grp[(size_t)(m0 + lrow) * NGRP + gbase + gA], bestA);
                    atomicMin(&g_grp[(size_t)(m0 + lrow) * NGRP + gbase + gA + 1], bestB);
                }
            }
        }
    } else {
#pragma unroll
        for (int ii = 0; ii < 8; ii++) {
            int p = (ii + mg) & 7;
            int row = rbase + p;
            float z2v = g_z2[m0 + row];
            unsigned long long best = ~0ull;
#pragma unroll
            for (int jj = 0; jj < 8; jj++) {
                int t = (jj + 2 * ng) & 7;
                int kc = n0 + 96 + ng * 8 + t;
                float s = __fadd_rn(__fadd_rn(z2v, __ldg(&g_e2[kc])), facc[ii][jj] * EZ_UNSCALE);
                unsigned long long pk = ((unsigned long long)__float_as_uint(s) << 32) | (unsigned)kc;
                if (pk < best) best = pk;
            }
#pragma unroll
            for (int off = 1; off < 4; off <<= 1) {
                unsigned long long o = __shfl_xor_sync(0xffffffffu, best, off);
                if (o < best) best = o;
            }
            if (ng == 0)
                atomicMin(&g_grp[(size_t)(m0 + row) * NGRP + gbase + 3], best);
        }
    }
}

// ---------------- rescue: exact re-score of near-min groups (bit-exact R2 chain) ----------------
__global__ __launch_bounds__(256) void rescue_kernel(const float* __restrict__ z,
                                                     const float* __restrict__ cb) {
    const int lane = threadIdx.x & 31;
    const int n = blockIdx.x * 8 + (threadIdx.x >> 5);
    const unsigned long long* base = g_grp + (size_t)n * NGRP;

    unsigned long long gm[8];
    unsigned long long mn = ~0ull;
#pragma unroll
    for (int j = 0; j < 8; j++) {
        gm[j] = base[lane + 32 * j];
        if (gm[j] < mn) mn = gm[j];
    }
#pragma unroll
    for (int off = 16; off > 0; off >>= 1) {
        unsigned long long o = __shfl_xor_sync(0xffffffffu, mn, off);
        if (o < mn) mn = o;
    }
    const float T = __uint_as_float((unsigned)(mn >> 32)) + RESCUE_MARGIN;

    const int b = n >> 11, l = n & 2047;
    const float z2v = g_z2[n];
    const float* zp = z + (size_t)b * (DD * LL) + l;
    unsigned long long best = ~0ull;

#pragma unroll
    for (int j = 0; j < 8; j++) {
        unsigned flag = __ballot_sync(0xffffffffu,
                                      __uint_as_float((unsigned)(gm[j] >> 32)) <= T);
        while (flag) {
            int g = 32 * j + (__ffs(flag) - 1);
            flag &= flag - 1;
            int k = g * 32 + lane;
            const float4* crow = reinterpret_cast<const float4*>(cb + (size_t)k * DD);
            float acc = 0.f;
            const float* zq = zp;
#pragma unroll 4
            for (int d4 = 0; d4 < DD / 4; d4++) {
                float4 c4 = __ldg(&crow[d4]);
                float za = zq[0], zb = zq[LL], zc = zq[2 * LL], zd = zq[3 * LL];
                acc = fmaf(za, c4.x, acc);
                acc = fmaf(zb, c4.y, acc);
                acc = fmaf(zc, c4.z, acc);
                acc = fmaf(zd, c4.w, acc);
                zq += 4 * LL;
            }
            float s = __fadd_rn(__fadd_rn(z2v, g_e2[k]), -2.0f * acc);
            unsigned long long p = ((unsigned long long)__float_as_uint(s) << 32) | (unsigned)k;
            if (p < best) best = p;
        }
    }
#pragma unroll
    for (int off = 16; off > 0; off >>= 1) {
        unsigned long long o = __shfl_xor_sync(0xffffffffu, best, off);
        if (o < best) best = o;
    }
    if (lane == 0) g_idx[n] = (int)(best & 0xFFFFFFFFull);
}

// ---------------- output + loss (bit-exact) ----------------
__global__ void out_loss_kernel(const float* __restrict__ z,
                                const float* __restrict__ cb,
                                float* __restrict__ out) {
    double acc = 0.0;
    int stride = gridDim.x * blockDim.x;
    for (int e = blockIdx.x * blockDim.x + threadIdx.x; e < NTOT; e += stride) {
        int l = e & 2047;
        int d = (e >> 11) & 255;
        int b = e >> 19;
        int id = g_idx[(b << 11) | l];
        float ze = z[e];
        float zq = cb[(size_t)id * DD + d];
        float df = __fsub_rn(zq, ze);
        out[e] = __fadd_rn(ze, df);
        acc += (double)__fmul_rn(df, df);
    }
#pragma unroll
    for (int o = 16; o > 0; o >>= 1) acc += __shfl_down_sync(0xffffffffu, acc, o);
    __shared__ double red[8];
    int lane = threadIdx.x & 31, w = threadIdx.x >> 5;
    if (lane == 0) red[w] = acc;
    __syncthreads();
    if (w == 0) {
        double v = (lane < 8) ? red[lane] : 0.0;
#pragma unroll
        for (int o = 4; o > 0; o >>= 1) v += __shfl_down_sync(0xffffffffu, v, o);
        if (lane == 0) atomicAdd(&g_loss, v);
    }
}

__global__ void finalize_kernel(float* __restrict__ out, int out_size) {
    double m = g_loss / (double)NTOT;
    float mf = (float)m;
    float vq = __fadd_rn(__fmul_rn(mf, 0.25f), mf);
    if (out_size > NTOT) out[NTOT] = vq;
}

// ---------------- host ----------------
extern "C" void kernel_launch(void* const* d_in, const int* in_sizes, int n_in,
                              void* d_out, int out_size) {
    const float* z  = (const float*)d_in[0];
    const float* cb = (const float*)d_in[1];
    float* out = (float*)d_out;

    cudaFuncSetAttribute(vq_mma_kernel, cudaFuncAttributeMaxDynamicSharedMemorySize, DYNSMEM);

    reset_kernel<<<1, 1>>>();
    init_grp_kernel<<<(int)((size_t)NN * NGRP / 2 / 256), 256>>>();
    e2_kernel<<<KK / 8, 256>>>(cb);
    z2_kernel<<<NN / 256, 256>>>(z);
    prep_c_kernel<<<KK * DD / 4 / 256, 256>>>(cb);
    prep_z_kernel<<<NN * (DD / 4) / 256, 256>>>(z);
    dim3 grid(NN / BM, KK / BN);
    vq_mma_kernel<<<grid, NTHREADS, DYNSMEM>>>();
    rescue_kernel<<<NN / 8, 256>>>(z, cb);
    out_loss_kernel<<<1184, 256>>>(z, cb, out);
    finalize_kernel<<<1, 1>>>(out, out_size);
}

// round 10
// speedup vs baseline: 2.4276x; 2.4276x over previous
#include <cuda_runtime.h>
#include <cuda_fp16.h>
#include <cstdint>

#define NB 16
#define DD 256
#define LL 2048
#define KK 8192
#define NN (NB*LL)        // 32768 z vectors
#define NTOT (NB*DD*LL)
#define BM 256
#define BN 128
#define BKH 64            // k halves per stage
#define NKITER (DD/BKH)   // 4
#define HSTRIDE 72        // padded halves per row (conflict-free)
#define A_HALFS (BM*HSTRIDE)
#define B_HALFS (BN*HSTRIDE)
#define STAGE_HALFS (A_HALFS+B_HALFS)
#define STAGE_BYTES (STAGE_HALFS*2)       // 55296
#define NSTAGE 3
#define DYNSMEM (NSTAGE*STAGE_BYTES)      // 165888
#define NGRP 256
#define RESCUE_MARGIN 2e-4f
#define EZ_UNSCALE (-0.000244140625f)     // -2 * 2^-13 (exact)
#define NTHREADS 512

// ---------------- device scratch ----------------
__device__ __align__(1024) __half g_zH[(size_t)NN*DD];  // fp16 z   [n][d]
__device__ __align__(1024) __half g_cH[(size_t)KK*DD];  // fp16 cb*8192 [k][d]
__device__ unsigned long long g_grp[(size_t)NN*NGRP];   // per-group packed minima
__device__ float  g_z2[NN];
__device__ float  g_e2[KK];
__device__ int    g_idx[NN];
__device__ double g_loss;

// ---------------- helpers ----------------
__device__ __forceinline__ uint32_t smem_u32(const void* p) {
    uint32_t a;
    asm("{ .reg .u64 t; cvta.to.shared.u64 t, %1; cvt.u32.u64 %0, t; }" : "=r"(a) : "l"(p));
    return a;
}
#define CP_ASYNC16(sa, gp) \
    asm volatile("cp.async.cg.shared.global [%0], [%1], 16;" :: "r"(sa), "l"(gp) : "memory")
#define CP_COMMIT() asm volatile("cp.async.commit_group;" ::: "memory")
#define CP_WAIT1()  asm volatile("cp.async.wait_group 1;" ::: "memory")
#define CP_WAIT0()  asm volatile("cp.async.wait_group 0;" ::: "memory")

__device__ __forceinline__ void mma_f16(float* c, const uint32_t* a, const uint32_t* b) {
    asm volatile(
        "mma.sync.aligned.m16n8k16.row.col.f32.f16.f16.f32 "
        "{%0,%1,%2,%3}, {%4,%5,%6,%7}, {%8,%9}, {%0,%1,%2,%3};"
        : "+f"(c[0]), "+f"(c[1]), "+f"(c[2]), "+f"(c[3])
        : "r"(a[0]), "r"(a[1]), "r"(a[2]), "r"(a[3]), "r"(b[0]), "r"(b[1]));
}

// ---------------- prep / small kernels (R2-validated numerics) ----------------
__global__ void reset_kernel() { g_loss = 0.0; }

__global__ void e2_kernel(const float* __restrict__ cb) {
    int warp = blockIdx.x * 8 + (threadIdx.x >> 5);
    int lane = threadIdx.x & 31;
    const float* r = cb + (size_t)warp * DD;
    float s = 0.f;
#pragma unroll
    for (int i = 0; i < DD / 32; i++) { float v = r[lane + i * 32]; s = fmaf(v, v, s); }
#pragma unroll
    for (int o = 16; o > 0; o >>= 1) s += __shfl_down_sync(0xffffffffu, s, o);
    if (lane == 0) g_e2[warp] = s;
}

// sequential-d, separate mul/add roundings (bit-exact vs reference); unroll 32 for MLP
__global__ void z2_kernel(const float* __restrict__ z) {
    int n = blockIdx.x * 256 + threadIdx.x;
    int b = n >> 11, l = n & 2047;
    const float* p = z + (size_t)b * (DD * LL) + l;
    float s = 0.f;
#pragma unroll 32
    for (int d = 0; d < DD; d++) {
        float v = __ldg(&p[(size_t)d * LL]);
        s = __fadd_rn(s, __fmul_rn(v, v));
    }
    g_z2[n] = s;
}

__global__ void prep_c_kernel(const float* __restrict__ cb) {
    int i = blockIdx.x * 256 + threadIdx.x;       // over KK*DD/4
    float4 v = reinterpret_cast<const float4*>(cb)[i];
    __half2 h0 = __floats2half2_rn(v.x * 8192.f, v.y * 8192.f);
    __half2 h1 = __floats2half2_rn(v.z * 8192.f, v.w * 8192.f);
    reinterpret_cast<__half2*>(g_cH)[i * 2]     = h0;
    reinterpret_cast<__half2*>(g_cH)[i * 2 + 1] = h1;
}

__global__ void prep_z_kernel(const float* __restrict__ z) {
    int gid = blockIdx.x * 256 + threadIdx.x;     // NN*64 threads
    int n  = gid & (NN - 1);
    int d0 = (gid >> 15) << 2;
    int b = n >> 11, l = n & 2047;
    const float* p = z + ((size_t)b * DD + d0) * LL + l;
    float x0 = p[0], x1 = p[LL], x2 = p[2 * LL], x3 = p[3 * LL];
    __half2* o = reinterpret_cast<__half2*>(&g_zH[(size_t)n * DD + d0]);
    o[0] = __floats2half2_rn(x0, x1);
    o[1] = __floats2half2_rn(x2, x3);
}

// ---------------- main GEMM (fp16 mma.sync, f32 acc, 16 warps of 64x32) ----------------
__device__ __forceinline__ void stage_load(__half* buf, int m0, int n0, int kk0, int tid) {
#pragma unroll
    for (int it = 0; it < 4; it++) {              // A: 256 rows x 128B
        int idx = tid + it * NTHREADS;
        int row = idx >> 3, ch = (idx & 7) << 3;
        uint32_t sa = smem_u32(buf + row * HSTRIDE + ch);
        CP_ASYNC16(sa, &g_zH[(size_t)(m0 + row) * DD + kk0 + ch]);
    }
#pragma unroll
    for (int it = 0; it < 2; it++) {              // B: 128 rows x 128B
        int idx = tid + it * NTHREADS;
        int row = idx >> 3, ch = (idx & 7) << 3;
        uint32_t sa = smem_u32(buf + A_HALFS + row * HSTRIDE + ch);
        CP_ASYNC16(sa, &g_cH[(size_t)(n0 + row) * DD + kk0 + ch]);
    }
}

__global__ __launch_bounds__(NTHREADS, 1) void vq_mma_kernel() {
    extern __shared__ __align__(16) __half hsm[];
    const int tid = threadIdx.x;
    const int wid = tid >> 5, lane = tid & 31;
    const int warpM = wid >> 2, warpN = wid & 3;   // 4x4 warp grid: 64 rows x 32 cols
    const int q = lane >> 2, r = lane & 3;
    const int m0 = blockIdx.x * BM;
    const int n0 = blockIdx.y * BN;

    float c[4][4][4];
#pragma unroll
    for (int i = 0; i < 4; i++)
#pragma unroll
        for (int j = 0; j < 4; j++)
#pragma unroll
            for (int t = 0; t < 4; t++) c[i][j][t] = 0.f;

    stage_load(hsm, m0, n0, 0, tid); CP_COMMIT();
    stage_load(hsm + STAGE_HALFS, m0, n0, BKH, tid); CP_COMMIT();

    for (int i = 0; i < NKITER; i++) {
        if (i < NKITER - 1) CP_WAIT1(); else CP_WAIT0();
        __syncthreads();
        if (i + 2 < NKITER) {
            stage_load(hsm + ((i + 2) % NSTAGE) * STAGE_HALFS, m0, n0, (i + 2) * BKH, tid);
            CP_COMMIT();
        }
        const __half* As = hsm + (i % NSTAGE) * STAGE_HALFS;
        const __half* Bs = As + A_HALFS;
#pragma unroll
        for (int kb = 0; kb < BKH; kb += 16) {
            uint32_t a[4][4], b[4][2];
#pragma unroll
            for (int mf = 0; mf < 4; mf++) {
                int r0 = warpM * 64 + mf * 16 + q;
                a[mf][0] = *reinterpret_cast<const uint32_t*>(&As[r0 * HSTRIDE + kb + 2 * r]);
                a[mf][1] = *reinterpret_cast<const uint32_t*>(&As[(r0 + 8) * HSTRIDE + kb + 2 * r]);
                a[mf][2] = *reinterpret_cast<const uint32_t*>(&As[r0 * HSTRIDE + kb + 2 * r + 8]);
                a[mf][3] = *reinterpret_cast<const uint32_t*>(&As[(r0 + 8) * HSTRIDE + kb + 2 * r + 8]);
            }
#pragma unroll
            for (int nf = 0; nf < 4; nf++) {
                int cc = warpN * 32 + nf * 8 + q;
                b[nf][0] = *reinterpret_cast<const uint32_t*>(&Bs[cc * HSTRIDE + kb + 2 * r]);
                b[nf][1] = *reinterpret_cast<const uint32_t*>(&Bs[cc * HSTRIDE + kb + 2 * r + 8]);
            }
#pragma unroll
            for (int mf = 0; mf < 4; mf++)
#pragma unroll
                for (int nf = 0; nf < 4; nf++)
                    mma_f16(c[mf][nf], a[mf], b[nf]);
        }
        __syncthreads();
    }

    // ---- epilogue: each warp's 32 codes == exactly one group -> plain store, no atomics ----
    const int grp = blockIdx.y * 4 + warpN;
#pragma unroll
    for (int mf = 0; mf < 4; mf++) {
#pragma unroll
        for (int half = 0; half < 2; half++) {
            int lrow = warpM * 64 + mf * 16 + q + half * 8;
            float z2v = g_z2[m0 + lrow];
            unsigned long long best = ~0ull;
#pragma unroll
            for (int nf = 0; nf < 4; nf++) {
                int k0 = n0 + warpN * 32 + nf * 8 + 2 * r;
                float e20 = __ldg(&g_e2[k0]);
                float e21 = __ldg(&g_e2[k0 + 1]);
                float s0 = __fadd_rn(__fadd_rn(z2v, e20), c[mf][nf][half * 2 + 0] * EZ_UNSCALE);
                float s1 = __fadd_rn(__fadd_rn(z2v, e21), c[mf][nf][half * 2 + 1] * EZ_UNSCALE);
                unsigned long long p0 = ((unsigned long long)__float_as_uint(s0) << 32) | (unsigned)k0;
                unsigned long long p1 = ((unsigned long long)__float_as_uint(s1) << 32) | (unsigned)(k0 + 1);
                if (p0 < best) best = p0;
                if (p1 < best) best = p1;
            }
#pragma unroll
            for (int off = 1; off < 4; off <<= 1) {
                unsigned long long o = __shfl_xor_sync(0xffffffffu, best, off);
                if (o < best) best = o;
            }
            if (r == 0)
                g_grp[(size_t)(m0 + lrow) * NGRP + grp] = best;
        }
    }
}

// ---------------- rescue: exact re-score of near-min groups (bit-exact R2 chain) ----------------
__global__ __launch_bounds__(256) void rescue_kernel(const float* __restrict__ z,
                                                     const float* __restrict__ cb) {
    const int lane = threadIdx.x & 31;
    const int n = blockIdx.x * 8 + (threadIdx.x >> 5);
    const unsigned long long* base = g_grp + (size_t)n * NGRP;

    unsigned long long gm[8];
    unsigned long long mn = ~0ull;
#pragma unroll
    for (int j = 0; j < 8; j++) {
        gm[j] = base[lane + 32 * j];
        if (gm[j] < mn) mn = gm[j];
    }
#pragma unroll
    for (int off = 16; off > 0; off >>= 1) {
        unsigned long long o = __shfl_xor_sync(0xffffffffu, mn, off);
        if (o < mn) mn = o;
    }
    const float T = __uint_as_float((unsigned)(mn >> 32)) + RESCUE_MARGIN;

    const int b = n >> 11, l = n & 2047;
    const float z2v = g_z2[n];
    const float* zp = z + (size_t)b * (DD * LL) + l;
    unsigned long long best = ~0ull;

#pragma unroll
    for (int j = 0; j < 8; j++) {
        unsigned flag = __ballot_sync(0xffffffffu,
                                      __uint_as_float((unsigned)(gm[j] >> 32)) <= T);
        while (flag) {
            int g = 32 * j + (__ffs(flag) - 1);
            flag &= flag - 1;
            int k = g * 32 + lane;
            const float4* crow = reinterpret_cast<const float4*>(cb + (size_t)k * DD);
            float acc = 0.f;
            const float* zq = zp;
#pragma unroll 4
            for (int d4 = 0; d4 < DD / 4; d4++) {
                float4 c4 = __ldg(&crow[d4]);
                float za = zq[0], zb = zq[LL], zc = zq[2 * LL], zd = zq[3 * LL];
                acc = fmaf(za, c4.x, acc);
                acc = fmaf(zb, c4.y, acc);
                acc = fmaf(zc, c4.z, acc);
                acc = fmaf(zd, c4.w, acc);
                zq += 4 * LL;
            }
            float s = __fadd_rn(__fadd_rn(z2v, g_e2[k]), -2.0f * acc);
            unsigned long long p = ((unsigned long long)__float_as_uint(s) << 32) | (unsigned)k;
            if (p < best) best = p;
        }
    }
#pragma unroll
    for (int off = 16; off > 0; off >>= 1) {
        unsigned long long o = __shfl_xor_sync(0xffffffffu, best, off);
        if (o < best) best = o;
    }
    if (lane == 0) g_idx[n] = (int)(best & 0xFFFFFFFFull);
}

// ---------------- output + loss (bit-exact) ----------------
__global__ void out_loss_kernel(const float* __restrict__ z,
                                const float* __restrict__ cb,
                                float* __restrict__ out) {
    double acc = 0.0;
    int stride = gridDim.x * blockDim.x;
    for (int e = blockIdx.x * blockDim.x + threadIdx.x; e < NTOT; e += stride) {
        int l = e & 2047;
        int d = (e >> 11) & 255;
        int b = e >> 19;
        int id = g_idx[(b << 11) | l];
        float ze = z[e];
        float zq = cb[(size_t)id * DD + d];
        float df = __fsub_rn(zq, ze);
        out[e] = __fadd_rn(ze, df);
        acc += (double)__fmul_rn(df, df);
    }
#pragma unroll
    for (int o = 16; o > 0; o >>= 1) acc += __shfl_down_sync(0xffffffffu, acc, o);
    __shared__ double red[8];
    int lane = threadIdx.x & 31, w = threadIdx.x >> 5;
    if (lane == 0) red[w] = acc;
    __syncthreads();
    if (w == 0) {
        double v = (lane < 8) ? red[lane] : 0.0;
#pragma unroll
        for (int o = 4; o > 0; o >>= 1) v += __shfl_down_sync(0xffffffffu, v, o);
        if (lane == 0) atomicAdd(&g_loss, v);
    }
}

__global__ void finalize_kernel(float* __restrict__ out, int out_size) {
    double m = g_loss / (double)NTOT;
    float mf = (float)m;
    float vq = __fadd_rn(__fmul_rn(mf, 0.25f), mf);
    if (out_size > NTOT) out[NTOT] = vq;
}

// ---------------- host ----------------
extern "C" void kernel_launch(void* const* d_in, const int* in_sizes, int n_in,
                              void* d_out, int out_size) {
    const float* z  = (const float*)d_in[0];
    const float* cb = (const float*)d_in[1];
    float* out = (float*)d_out;

    cudaFuncSetAttribute(vq_mma_kernel, cudaFuncAttributeMaxDynamicSharedMemorySize, DYNSMEM);

    reset_kernel<<<1, 1>>>();
    e2_kernel<<<KK / 8, 256>>>(cb);
    z2_kernel<<<NN / 256, 256>>>(z);
    prep_c_kernel<<<KK * DD / 4 / 256, 256>>>(cb);
    prep_z_kernel<<<NN * (DD / 4) / 256, 256>>>(z);
    dim3 grid(NN / BM, KK / BN);
    vq_mma_kernel<<<grid, NTHREADS, DYNSMEM>>>();
    rescue_kernel<<<NN / 8, 256>>>(z, cb);
    out_loss_kernel<<<1184, 256>>>(z, cb, out);
    finalize_kernel<<<1, 1>>>(out, out_size);
}

// round 11
// speedup vs baseline: 2.6456x; 1.0898x over previous
#include <cuda_runtime.h>
#include <cuda_fp16.h>
#include <cstdint>

#define NB 16
#define DD 256
#define LL 2048
#define KK 8192
#define NN (NB*LL)        // 32768 z vectors
#define NTOT (NB*DD*LL)
#define BM 256
#define BN 128
#define BKH 64
#define NKITER (DD/BKH)   // 4
#define HSTRIDE 72
#define A_HALFS (BM*HSTRIDE)
#define B_HALFS (BN*HSTRIDE)
#define STAGE_HALFS (A_HALFS+B_HALFS)
#define STAGE_BYTES (STAGE_HALFS*2)       // 55296
#define NSTAGE 3
#define DYNSMEM (NSTAGE*STAGE_BYTES)      // 165888
#define NGRP 256
#define RESCUE_MARGIN 2e-4f
#define EZ_UNSCALE (-0.000244140625f)     // -2 * 2^-13 (exact)

// ---------------- device scratch ----------------
__device__ __align__(1024) float  g_zT[(size_t)NN*DD];  // 32MB fp32 z  [n][d] (bitwise copy)
__device__ __align__(1024) __half g_zH[(size_t)NN*DD];  // 16MB fp16 z  [n][d]
__device__ __align__(1024) __half g_cH[(size_t)KK*DD];  // 4MB fp16 cb*8192
__device__ float  g_grp[(size_t)NN*NGRP];               // 33.5MB per-group approx minima
__device__ float  g_z2[NN];
__device__ float  g_e2[KK];
__device__ int    g_idx[NN];
__device__ double g_loss;

// ---------------- helpers ----------------
__device__ __forceinline__ uint32_t smem_u32(const void* p) {
    uint32_t a;
    asm("{ .reg .u64 t; cvta.to.shared.u64 t, %1; cvt.u32.u64 %0, t; }" : "=r"(a) : "l"(p));
    return a;
}
#define CP_ASYNC16(sa, gp) \
    asm volatile("cp.async.cg.shared.global [%0], [%1], 16;" :: "r"(sa), "l"(gp) : "memory")
#define CP_COMMIT() asm volatile("cp.async.commit_group;" ::: "memory")
#define CP_WAIT1()  asm volatile("cp.async.wait_group 1;" ::: "memory")
#define CP_WAIT0()  asm volatile("cp.async.wait_group 0;" ::: "memory")

__device__ __forceinline__ void mma_f16(float* c, const uint32_t* a, const uint32_t* b) {
    asm volatile(
        "mma.sync.aligned.m16n8k16.row.col.f32.f16.f16.f32 "
        "{%0,%1,%2,%3}, {%4,%5,%6,%7}, {%8,%9}, {%0,%1,%2,%3};"
        : "+f"(c[0]), "+f"(c[1]), "+f"(c[2]), "+f"(c[3])
        : "r"(a[0]), "r"(a[1]), "r"(a[2]), "r"(a[3]), "r"(b[0]), "r"(b[1]));
}

// ---------------- fused z prep: transpose + fp16 + z2 (exact order) + loss reset ----------------
__global__ __launch_bounds__(128) void zprep_kernel(const float* __restrict__ z) {
    __shared__ float s[64][129];
    const int tid = threadIdx.x;
    const int w = tid >> 5, lane = tid & 31;
    const int n0 = blockIdx.x * 128;
    const int b = n0 >> 11, l0 = n0 & 2047;
    const float* zb = z + (size_t)b * DD * LL + l0;
    if (blockIdx.x == 0 && tid == 0) g_loss = 0.0;

    float acc = 0.f;
    for (int c = 0; c < 4; c++) {
        __syncthreads();
#pragma unroll
        for (int i = 0; i < 16; i++) {            // load 64 d-rows x 128 l, coalesced
            int f4 = tid + i * 128;
            int dd = f4 >> 5, l4 = (f4 & 31) << 2;
            float4 v = *reinterpret_cast<const float4*>(&zb[(size_t)(c * 64 + dd) * LL + l4]);
            s[dd][l4] = v.x; s[dd][l4 + 1] = v.y; s[dd][l4 + 2] = v.z; s[dd][l4 + 3] = v.w;
        }
        __syncthreads();
#pragma unroll 16
        for (int dd = 0; dd < 64; dd++) {         // z2 partial, sequential d (bit-exact)
            float v = s[dd][tid];
            acc = __fadd_rn(acc, __fmul_rn(v, v));
        }
#pragma unroll 8
        for (int j = 0; j < 32; j++) {            // transposed coalesced writes
            int row = w + 4 * j;
            float a0 = s[2 * lane][row];
            float a1 = s[2 * lane + 1][row];
            size_t o = (size_t)(n0 + row) * DD + c * 64 + 2 * lane;
            *reinterpret_cast<float2*>(&g_zT[o]) = make_float2(a0, a1);
            *reinterpret_cast<__half2*>(&g_zH[o]) = __floats2half2_rn(a0, a1);
        }
    }
    g_z2[n0 + tid] = acc;
}

// ---------------- e2 + codebook fp16 (orders preserved from validated R2/R6) ----------------
__global__ void e2_kernel(const float* __restrict__ cb) {
    int warp = blockIdx.x * 8 + (threadIdx.x >> 5);
    int lane = threadIdx.x & 31;
    const float* r = cb + (size_t)warp * DD;
    float s = 0.f;
#pragma unroll
    for (int i = 0; i < DD / 32; i++) { float v = r[lane + i * 32]; s = fmaf(v, v, s); }
#pragma unroll
    for (int o = 16; o > 0; o >>= 1) s += __shfl_down_sync(0xffffffffu, s, o);
    if (lane == 0) g_e2[warp] = s;
}

__global__ void prep_c_kernel(const float* __restrict__ cb) {
    int i = blockIdx.x * 256 + threadIdx.x;
    float4 v = reinterpret_cast<const float4*>(cb)[i];
    __half2 h0 = __floats2half2_rn(v.x * 8192.f, v.y * 8192.f);
    __half2 h1 = __floats2half2_rn(v.z * 8192.f, v.w * 8192.f);
    reinterpret_cast<__half2*>(g_cH)[i * 2]     = h0;
    reinterpret_cast<__half2*>(g_cH)[i * 2 + 1] = h1;
}

// ---------------- main GEMM (R6-proven: fp16 mma, f32 acc, 256 threads) ----------------
__device__ __forceinline__ void stage_load(__half* buf, int m0, int n0, int kk0, int tid) {
#pragma unroll
    for (int it = 0; it < 8; it++) {
        int idx = tid + it * 256;
        int row = idx >> 3, ch = (idx & 7) << 3;
        uint32_t sa = smem_u32(buf + row * HSTRIDE + ch);
        CP_ASYNC16(sa, &g_zH[(size_t)(m0 + row) * DD + kk0 + ch]);
    }
#pragma unroll
    for (int it = 0; it < 4; it++) {
        int idx = tid + it * 256;
        int row = idx >> 3, ch = (idx & 7) << 3;
        uint32_t sa = smem_u32(buf + A_HALFS + row * HSTRIDE + ch);
        CP_ASYNC16(sa, &g_cH[(size_t)(n0 + row) * DD + kk0 + ch]);
    }
}

__global__ __launch_bounds__(256, 1) void vq_mma_kernel() {
    extern __shared__ __align__(16) __half hsm[];
    const int tid = threadIdx.x;
    const int wid = tid >> 5, lane = tid & 31;
    const int warpM = wid >> 1, warpN = wid & 1;
    const int q = lane >> 2, r = lane & 3;
    const int m0 = blockIdx.x * BM;
    const int n0 = blockIdx.y * BN;

    float c[4][8][4];
#pragma unroll
    for (int i = 0; i < 4; i++)
#pragma unroll
        for (int j = 0; j < 8; j++)
#pragma unroll
            for (int t = 0; t < 4; t++) c[i][j][t] = 0.f;

    stage_load(hsm, m0, n0, 0, tid); CP_COMMIT();
    stage_load(hsm + STAGE_HALFS, m0, n0, BKH, tid); CP_COMMIT();

    for (int i = 0; i < NKITER; i++) {
        if (i < NKITER - 1) CP_WAIT1(); else CP_WAIT0();
        __syncthreads();
        if (i + 2 < NKITER) {
            stage_load(hsm + ((i + 2) % NSTAGE) * STAGE_HALFS, m0, n0, (i + 2) * BKH, tid);
            CP_COMMIT();
        }
        const __half* As = hsm + (i % NSTAGE) * STAGE_HALFS;
        const __half* Bs = As + A_HALFS;
#pragma unroll
        for (int kb = 0; kb < BKH; kb += 16) {
            uint32_t a[4][4], b[8][2];
#pragma unroll
            for (int mf = 0; mf < 4; mf++) {
                int r0 = warpM * 64 + mf * 16 + q;
                a[mf][0] = *reinterpret_cast<const uint32_t*>(&As[r0 * HSTRIDE + kb + 2 * r]);
                a[mf][1] = *reinterpret_cast<const uint32_t*>(&As[(r0 + 8) * HSTRIDE + kb + 2 * r]);
                a[mf][2] = *reinterpret_cast<const uint32_t*>(&As[r0 * HSTRIDE + kb + 2 * r + 8]);
                a[mf][3] = *reinterpret_cast<const uint32_t*>(&As[(r0 + 8) * HSTRIDE + kb + 2 * r + 8]);
            }
#pragma unroll
            for (int nf = 0; nf < 8; nf++) {
                int cc = warpN * 64 + nf * 8 + q;
                b[nf][0] = *reinterpret_cast<const uint32_t*>(&Bs[cc * HSTRIDE + kb + 2 * r]);
                b[nf][1] = *reinterpret_cast<const uint32_t*>(&Bs[cc * HSTRIDE + kb + 2 * r + 8]);
            }
#pragma unroll
            for (int mf = 0; mf < 4; mf++)
#pragma unroll
                for (int nf = 0; nf < 8; nf++)
                    mma_f16(c[mf][nf], a[mf], b[nf]);
        }
        __syncthreads();
    }

    // ---- epilogue: per-(row, 32-code group) float minima (score only) ----
#pragma unroll
    for (int mf = 0; mf < 4; mf++) {
#pragma unroll
        for (int half = 0; half < 2; half++) {
            int lrow = warpM * 64 + mf * 16 + q + half * 8;
            float z2v = g_z2[m0 + lrow];
#pragma unroll
            for (int nfh = 0; nfh < 2; nfh++) {
                float best = 3.4e38f;
#pragma unroll
                for (int nfo = 0; nfo < 4; nfo++) {
                    int nf = nfh * 4 + nfo;
                    int k0 = n0 + warpN * 64 + nf * 8 + 2 * r;
                    float e20 = __ldg(&g_e2[k0]);
                    float e21 = __ldg(&g_e2[k0 + 1]);
                    float s0 = __fadd_rn(__fadd_rn(z2v, e20), c[mf][nf][half * 2 + 0] * EZ_UNSCALE);
                    float s1 = __fadd_rn(__fadd_rn(z2v, e21), c[mf][nf][half * 2 + 1] * EZ_UNSCALE);
                    best = fminf(best, fminf(s0, s1));
                }
#pragma unroll
                for (int off = 1; off < 4; off <<= 1)
                    best = fminf(best, __shfl_xor_sync(0xffffffffu, best, off));
                if (r == 0)
                    g_grp[(size_t)(m0 + lrow) * NGRP + blockIdx.y * 4 + warpN * 2 + nfh] = best;
            }
        }
    }
}

// ---------------- rescue: exact re-score of near-min groups (bit-exact R2 chain) ----------------
__global__ __launch_bounds__(256) void rescue_kernel(const float* __restrict__ cb) {
    const int lane = threadIdx.x & 31;
    const int n = blockIdx.x * 8 + (threadIdx.x >> 5);
    const float* base = g_grp + (size_t)n * NGRP;

    float gm[8];
    float mn = 3.4e38f;
#pragma unroll
    for (int j = 0; j < 8; j++) {
        gm[j] = base[lane + 32 * j];
        mn = fminf(mn, gm[j]);
    }
#pragma unroll
    for (int off = 16; off > 0; off >>= 1)
        mn = fminf(mn, __shfl_xor_sync(0xffffffffu, mn, off));
    const float T = mn + RESCUE_MARGIN;

    const float z2v = g_z2[n];
    const float4* zr = reinterpret_cast<const float4*>(g_zT + (size_t)n * DD);
    unsigned long long best = ~0ull;

#pragma unroll
    for (int j = 0; j < 8; j++) {
        unsigned flag = __ballot_sync(0xffffffffu, gm[j] <= T);
        while (flag) {
            int g = 32 * j + (__ffs(flag) - 1);
            flag &= flag - 1;
            int k = g * 32 + lane;
            const float4* crow = reinterpret_cast<const float4*>(cb + (size_t)k * DD);
            float acc = 0.f;
#pragma unroll 8
            for (int d4 = 0; d4 < DD / 4; d4++) {
                float4 c4 = __ldg(&crow[d4]);
                float4 zv = zr[d4];
                acc = fmaf(zv.x, c4.x, acc);
                acc = fmaf(zv.y, c4.y, acc);
                acc = fmaf(zv.z, c4.z, acc);
                acc = fmaf(zv.w, c4.w, acc);
            }
            float s = __fadd_rn(__fadd_rn(z2v, g_e2[k]), -2.0f * acc);
            unsigned long long p = ((unsigned long long)__float_as_uint(s) << 32) | (unsigned)k;
            if (p < best) best = p;
        }
    }
#pragma unroll
    for (int off = 16; off > 0; off >>= 1) {
        unsigned long long o = __shfl_xor_sync(0xffffffffu, best, off);
        if (o < best) best = o;
    }
    if (lane == 0) g_idx[n] = (int)(best & 0xFFFFFFFFull);
}

// ---------------- output + loss: coalesced gather + smem-transposed writes ----------------
__global__ __launch_bounds__(256) void out_loss_kernel(const float* __restrict__ cb,
                                                       float* __restrict__ out) {
    __shared__ float so[32][257];
    __shared__ double red[8];
    const int tid = threadIdx.x, wid = tid >> 5, lane = tid & 31;
    const int n0 = blockIdx.x * 32;
    const int b = n0 >> 11, l0 = n0 & 2047;
    double lacc = 0.0;
    const int perm = lane >> 2;

#pragma unroll
    for (int it = 0; it < 4; it++) {
        int li = wid * 4 + it;
        int n = n0 + li;
        int id = g_idx[n];
        const float4* zr = reinterpret_cast<const float4*>(g_zT + (size_t)n * DD);
        const float4* cr = reinterpret_cast<const float4*>(cb + (size_t)id * DD);
#pragma unroll
        for (int sg = 0; sg < 2; sg++) {
            int d4 = lane * 2 + sg;           // d = d4*4 + j = lane*8 + sg*4 + j
            float4 zv = zr[d4];
            float4 cv = __ldg(&cr[d4]);
            float df0 = __fsub_rn(cv.x, zv.x); float o0 = __fadd_rn(zv.x, df0);
            float df1 = __fsub_rn(cv.y, zv.y); float o1 = __fadd_rn(zv.y, df1);
            float df2 = __fsub_rn(cv.z, zv.z); float o2 = __fadd_rn(zv.z, df2);
            float df3 = __fsub_rn(cv.w, zv.w); float o3 = __fadd_rn(zv.w, df3);
            lacc += (double)__fmul_rn(df0, df0);
            lacc += (double)__fmul_rn(df1, df1);
            lacc += (double)__fmul_rn(df2, df2);
            lacc += (double)__fmul_rn(df3, df3);
            int kb = sg * 4;
            so[li][lane * 8 + ((kb + 0 + perm) & 7)] = o0;
            so[li][lane * 8 + ((kb + 1 + perm) & 7)] = o1;
            so[li][lane * 8 + ((kb + 2 + perm) & 7)] = o2;
            so[li][lane * 8 + ((kb + 3 + perm) & 7)] = o3;
        }
    }
    __syncthreads();
#pragma unroll 8
    for (int i = 0; i < 32; i++) {
        int d = wid * 32 + i;
        int col = (d & 248) | ((d + (d >> 5)) & 7);
        out[((size_t)b * DD + d) * LL + l0 + lane] = so[lane][col];
    }
    // loss reduction
#pragma unroll
    for (int o = 16; o > 0; o >>= 1) lacc += __shfl_down_sync(0xffffffffu, lacc, o);
    if (lane == 0) red[wid] = lacc;
    __syncthreads();
    if (wid == 0) {
        double v = (lane < 8) ? red[lane] : 0.0;
#pragma unroll
        for (int o = 4; o > 0; o >>= 1) v += __shfl_down_sync(0xffffffffu, v, o);
        if (lane == 0) atomicAdd(&g_loss, v);
    }
}

__global__ void finalize_kernel(float* __restrict__ out, int out_size) {
    double m = g_loss / (double)NTOT;
    float mf = (float)m;
    float vq = __fadd_rn(__fmul_rn(mf, 0.25f), mf);
    if (out_size > NTOT) out[NTOT] = vq;
}

// ---------------- host ----------------
extern "C" void kernel_launch(void* const* d_in, const int* in_sizes, int n_in,
                              void* d_out, int out_size) {
    const float* z  = (const float*)d_in[0];
    const float* cb = (const float*)d_in[1];
    float* out = (float*)d_out;

    cudaFuncSetAttribute(vq_mma_kernel, cudaFuncAttributeMaxDynamicSharedMemorySize, DYNSMEM);

    zprep_kernel<<<NN / 128, 128>>>(z);
    e2_kernel<<<KK / 8, 256>>>(cb);
    prep_c_kernel<<<KK * DD / 4 / 256, 256>>>(cb);
    dim3 grid(NN / BM, KK / BN);
    vq_mma_kernel<<<grid, 256, DYNSMEM>>>();
    rescue_kernel<<<NN / 8, 256>>>(cb);
    out_loss_kernel<<<NN / 32, 256>>>(cb, out);
    finalize_kernel<<<1, 1>>>(out, out_size);
}

// round 12
// speedup vs baseline: 3.4293x; 1.2962x over previous
#include <cuda_runtime.h>
#include <cuda_fp16.h>
#include <cstdint>

#define NB 16
#define DD 256
#define LL 2048
#define KK 8192
#define NN (NB*LL)        // 32768 z vectors
#define NTOT (NB*DD*LL)
#define BM 256
#define BN 128
#define BKH 64
#define NKITER (DD/BKH)   // 4
#define HSTRIDE 72
#define A_HALFS (BM*HSTRIDE)
#define B_HALFS (BN*HSTRIDE)
#define STAGE_HALFS (A_HALFS+B_HALFS)
#define STAGE_BYTES (STAGE_HALFS*2)       // 55296
#define NSTAGE 3
#define DYNSMEM (NSTAGE*STAGE_BYTES)      // 165888
#define NGRP 1024                         // 8-code groups
#define RESCUE_MARGIN 2e-4f
#define EZ_UNSCALE (-0.000244140625f)     // -2 * 2^-13 (exact)

// ---------------- device scratch ----------------
__device__ __align__(1024) float  g_zT[(size_t)NN*DD];   // 32MB fp32 z [n][d]
__device__ __align__(1024) __half g_zH[(size_t)NN*DD];   // 16MB fp16 z [n][d]
__device__ __align__(1024) __half g_cH[(size_t)KK*DD];   // 4MB fp16 cb*8192
__device__ __align__(1024) float  g_grp[(size_t)NN*NGRP];// 134MB per-8-code-group minima
__device__ float  g_z2[NN];
__device__ float  g_e2[KK];
__device__ int    g_idx[NN];
__device__ double g_loss;

// ---------------- helpers ----------------
__device__ __forceinline__ uint32_t smem_u32(const void* p) {
    uint32_t a;
    asm("{ .reg .u64 t; cvta.to.shared.u64 t, %1; cvt.u32.u64 %0, t; }" : "=r"(a) : "l"(p));
    return a;
}
#define CP_ASYNC16(sa, gp) \
    asm volatile("cp.async.cg.shared.global [%0], [%1], 16;" :: "r"(sa), "l"(gp) : "memory")
#define CP_COMMIT() asm volatile("cp.async.commit_group;" ::: "memory")
#define CP_WAIT1()  asm volatile("cp.async.wait_group 1;" ::: "memory")
#define CP_WAIT0()  asm volatile("cp.async.wait_group 0;" ::: "memory")

__device__ __forceinline__ void mma_f16(float* c, const uint32_t* a, const uint32_t* b) {
    asm volatile(
        "mma.sync.aligned.m16n8k16.row.col.f32.f16.f16.f32 "
        "{%0,%1,%2,%3}, {%4,%5,%6,%7}, {%8,%9}, {%0,%1,%2,%3};"
        : "+f"(c[0]), "+f"(c[1]), "+f"(c[2]), "+f"(c[3])
        : "r"(a[0]), "r"(a[1]), "r"(a[2]), "r"(a[3]), "r"(b[0]), "r"(b[1]));
}

// ---------------- fused z prep: transpose + fp16 + z2 (exact order) + loss reset ----------------
__global__ __launch_bounds__(128) void zprep_kernel(const float* __restrict__ z) {
    __shared__ float s[64][129];
    const int tid = threadIdx.x;
    const int w = tid >> 5, lane = tid & 31;
    const int n0 = blockIdx.x * 128;
    const int b = n0 >> 11, l0 = n0 & 2047;
    const float* zb = z + (size_t)b * DD * LL + l0;
    if (blockIdx.x == 0 && tid == 0) g_loss = 0.0;

    float acc = 0.f;
    for (int c = 0; c < 4; c++) {
        __syncthreads();
#pragma unroll
        for (int i = 0; i < 16; i++) {
            int f4 = tid + i * 128;
            int dd = f4 >> 5, l4 = (f4 & 31) << 2;
            float4 v = *reinterpret_cast<const float4*>(&zb[(size_t)(c * 64 + dd) * LL + l4]);
            s[dd][l4] = v.x; s[dd][l4 + 1] = v.y; s[dd][l4 + 2] = v.z; s[dd][l4 + 3] = v.w;
        }
        __syncthreads();
#pragma unroll 16
        for (int dd = 0; dd < 64; dd++) {
            float v = s[dd][tid];
            acc = __fadd_rn(acc, __fmul_rn(v, v));
        }
#pragma unroll 8
        for (int j = 0; j < 32; j++) {
            int row = w + 4 * j;
            float a0 = s[2 * lane][row];
            float a1 = s[2 * lane + 1][row];
            size_t o = (size_t)(n0 + row) * DD + c * 64 + 2 * lane;
            *reinterpret_cast<float2*>(&g_zT[o]) = make_float2(a0, a1);
            *reinterpret_cast<__half2*>(&g_zH[o]) = __floats2half2_rn(a0, a1);
        }
    }
    g_z2[n0 + tid] = acc;
}

// ---------------- e2 + codebook fp16 (validated orders) ----------------
__global__ void e2_kernel(const float* __restrict__ cb) {
    int warp = blockIdx.x * 8 + (threadIdx.x >> 5);
    int lane = threadIdx.x & 31;
    const float* r = cb + (size_t)warp * DD;
    float s = 0.f;
#pragma unroll
    for (int i = 0; i < DD / 32; i++) { float v = r[lane + i * 32]; s = fmaf(v, v, s); }
#pragma unroll
    for (int o = 16; o > 0; o >>= 1) s += __shfl_down_sync(0xffffffffu, s, o);
    if (lane == 0) g_e2[warp] = s;
}

__global__ void prep_c_kernel(const float* __restrict__ cb) {
    int i = blockIdx.x * 256 + threadIdx.x;
    float4 v = reinterpret_cast<const float4*>(cb)[i];
    __half2 h0 = __floats2half2_rn(v.x * 8192.f, v.y * 8192.f);
    __half2 h1 = __floats2half2_rn(v.z * 8192.f, v.w * 8192.f);
    reinterpret_cast<__half2*>(g_cH)[i * 2]     = h0;
    reinterpret_cast<__half2*>(g_cH)[i * 2 + 1] = h1;
}

// ---------------- main GEMM (R6-proven mainloop; 8-code-group epilogue) ----------------
__device__ __forceinline__ void stage_load(__half* buf, int m0, int n0, int kk0, int tid) {
#pragma unroll
    for (int it = 0; it < 8; it++) {
        int idx = tid + it * 256;
        int row = idx >> 3, ch = (idx & 7) << 3;
        uint32_t sa = smem_u32(buf + row * HSTRIDE + ch);
        CP_ASYNC16(sa, &g_zH[(size_t)(m0 + row) * DD + kk0 + ch]);
    }
#pragma unroll
    for (int it = 0; it < 4; it++) {
        int idx = tid + it * 256;
        int row = idx >> 3, ch = (idx & 7) << 3;
        uint32_t sa = smem_u32(buf + A_HALFS + row * HSTRIDE + ch);
        CP_ASYNC16(sa, &g_cH[(size_t)(n0 + row) * DD + kk0 + ch]);
    }
}

__global__ __launch_bounds__(256, 1) void vq_mma_kernel() {
    extern __shared__ __align__(16) __half hsm[];
    const int tid = threadIdx.x;
    const int wid = tid >> 5, lane = tid & 31;
    const int warpM = wid >> 1, warpN = wid & 1;
    const int q = lane >> 2, r = lane & 3;
    const int m0 = blockIdx.x * BM;
    const int n0 = blockIdx.y * BN;

    float c[4][8][4];
#pragma unroll
    for (int i = 0; i < 4; i++)
#pragma unroll
        for (int j = 0; j < 8; j++)
#pragma unroll
            for (int t = 0; t < 4; t++) c[i][j][t] = 0.f;

    stage_load(hsm, m0, n0, 0, tid); CP_COMMIT();
    stage_load(hsm + STAGE_HALFS, m0, n0, BKH, tid); CP_COMMIT();

    for (int i = 0; i < NKITER; i++) {
        if (i < NKITER - 1) CP_WAIT1(); else CP_WAIT0();
        __syncthreads();
        if (i + 2 < NKITER) {
            stage_load(hsm + ((i + 2) % NSTAGE) * STAGE_HALFS, m0, n0, (i + 2) * BKH, tid);
            CP_COMMIT();
        }
        const __half* As = hsm + (i % NSTAGE) * STAGE_HALFS;
        const __half* Bs = As + A_HALFS;
#pragma unroll
        for (int kb = 0; kb < BKH; kb += 16) {
            uint32_t a[4][4], b[8][2];
#pragma unroll
            for (int mf = 0; mf < 4; mf++) {
                int r0 = warpM * 64 + mf * 16 + q;
                a[mf][0] = *reinterpret_cast<const uint32_t*>(&As[r0 * HSTRIDE + kb + 2 * r]);
                a[mf][1] = *reinterpret_cast<const uint32_t*>(&As[(r0 + 8) * HSTRIDE + kb + 2 * r]);
                a[mf][2] = *reinterpret_cast<const uint32_t*>(&As[r0 * HSTRIDE + kb + 2 * r + 8]);
                a[mf][3] = *reinterpret_cast<const uint32_t*>(&As[(r0 + 8) * HSTRIDE + kb + 2 * r + 8]);
            }
#pragma unroll
            for (int nf = 0; nf < 8; nf++) {
                int cc = warpN * 64 + nf * 8 + q;
                b[nf][0] = *reinterpret_cast<const uint32_t*>(&Bs[cc * HSTRIDE + kb + 2 * r]);
                b[nf][1] = *reinterpret_cast<const uint32_t*>(&Bs[cc * HSTRIDE + kb + 2 * r + 8]);
            }
#pragma unroll
            for (int mf = 0; mf < 4; mf++)
#pragma unroll
                for (int nf = 0; nf < 8; nf++)
                    mma_f16(c[mf][nf], a[mf], b[nf]);
        }
        __syncthreads();
    }

    // ---- epilogue: per-(row, 8-code group) minima, staged through smem ----
    float* sgrp = reinterpret_cast<float*>(hsm);   // [256][16] stride 20 (conflict-free, 16B-aligned)
#pragma unroll
    for (int mf = 0; mf < 4; mf++) {
#pragma unroll
        for (int half = 0; half < 2; half++) {
            int lrow = warpM * 64 + mf * 16 + q + half * 8;
            float z2v = g_z2[m0 + lrow];
#pragma unroll
            for (int nf = 0; nf < 8; nf++) {
                int k0 = n0 + warpN * 64 + nf * 8 + 2 * r;
                float e20 = __ldg(&g_e2[k0]);
                float e21 = __ldg(&g_e2[k0 + 1]);
                float s0 = __fadd_rn(__fadd_rn(z2v, e20), c[mf][nf][half * 2 + 0] * EZ_UNSCALE);
                float s1 = __fadd_rn(__fadd_rn(z2v, e21), c[mf][nf][half * 2 + 1] * EZ_UNSCALE);
                float best = fminf(s0, s1);
                best = fminf(best, __shfl_xor_sync(0xffffffffu, best, 1));
                best = fminf(best, __shfl_xor_sync(0xffffffffu, best, 2));
                if (r == 0)
                    sgrp[lrow * 20 + warpN * 8 + nf] = best;
            }
        }
    }
    __syncthreads();
    {   // coalesced-ish write: thread tid owns row tid (16 floats = 4 float4)
        float* dst = g_grp + (size_t)(m0 + tid) * NGRP + blockIdx.y * 16;
#pragma unroll
        for (int w4 = 0; w4 < 4; w4++) {
            float4 v = *reinterpret_cast<const float4*>(&sgrp[tid * 20 + w4 * 4]);
            reinterpret_cast<float4*>(dst)[w4] = v;
        }
    }
}

// ---------------- rescue: exact re-score of near-min 8-code groups (bit-exact chain) ----------------
__global__ __launch_bounds__(256) void rescue_kernel(const float* __restrict__ cb) {
    const int lane = threadIdx.x & 31;
    const int n = blockIdx.x * 8 + (threadIdx.x >> 5);
    const float4* base4 = reinterpret_cast<const float4*>(g_grp + (size_t)n * NGRP);

    float4 gm[8];
    float mn = 3.4e38f;
#pragma unroll
    for (int j = 0; j < 8; j++) {
        gm[j] = base4[lane + 32 * j];
        mn = fminf(mn, fminf(fminf(gm[j].x, gm[j].y), fminf(gm[j].z, gm[j].w)));
    }
#pragma unroll
    for (int off = 16; off > 0; off >>= 1)
        mn = fminf(mn, __shfl_xor_sync(0xffffffffu, mn, off));
    const float T = mn + RESCUE_MARGIN;

    const float z2v = g_z2[n];
    const float4* zr = reinterpret_cast<const float4*>(g_zT + (size_t)n * DD);
    unsigned long long best = ~0ull;

#pragma unroll
    for (int j = 0; j < 8; j++) {
        const float gv[4] = {gm[j].x, gm[j].y, gm[j].z, gm[j].w};
#pragma unroll
        for (int cc = 0; cc < 4; cc++) {
            unsigned flag = __ballot_sync(0xffffffffu, gv[cc] <= T);
            while (flag) {
                int src = __ffs(flag) - 1;
                flag &= flag - 1;
                int g = ((src + 32 * j) << 2) + cc;
                unsigned long long p = ~0ull;
                if (lane < 8) {
                    int k = g * 8 + lane;
                    const float4* crow = reinterpret_cast<const float4*>(cb + (size_t)k * DD);
                    float acc = 0.f;
#pragma unroll 8
                    for (int d4 = 0; d4 < DD / 4; d4++) {
                        float4 c4 = __ldg(&crow[d4]);
                        float4 zv = zr[d4];
                        acc = fmaf(zv.x, c4.x, acc);
                        acc = fmaf(zv.y, c4.y, acc);
                        acc = fmaf(zv.z, c4.z, acc);
                        acc = fmaf(zv.w, c4.w, acc);
                    }
                    float s = __fadd_rn(__fadd_rn(z2v, g_e2[k]), -2.0f * acc);
                    p = ((unsigned long long)__float_as_uint(s) << 32) | (unsigned)k;
                }
                if (p < best) best = p;
            }
        }
    }
#pragma unroll
    for (int off = 16; off > 0; off >>= 1) {
        unsigned long long o = __shfl_xor_sync(0xffffffffu, best, off);
        if (o < best) best = o;
    }
    if (lane == 0) g_idx[n] = (int)(best & 0xFFFFFFFFull);
}

// ---------------- output + loss: coalesced gather + smem-transposed writes ----------------
__global__ __launch_bounds__(256) void out_loss_kernel(const float* __restrict__ cb,
                                                       float* __restrict__ out) {
    __shared__ float so[32][257];
    __shared__ double red[8];
    const int tid = threadIdx.x, wid = tid >> 5, lane = tid & 31;
    const int n0 = blockIdx.x * 32;
    const int b = n0 >> 11, l0 = n0 & 2047;
    double lacc = 0.0;
    const int perm = lane >> 2;

#pragma unroll
    for (int it = 0; it < 4; it++) {
        int li = wid * 4 + it;
        int n = n0 + li;
        int id = g_idx[n];
        const float4* zr = reinterpret_cast<const float4*>(g_zT + (size_t)n * DD);
        const float4* cr = reinterpret_cast<const float4*>(cb + (size_t)id * DD);
#pragma unroll
        for (int sg = 0; sg < 2; sg++) {
            int d4 = lane * 2 + sg;
            float4 zv = zr[d4];
            float4 cv = __ldg(&cr[d4]);
            float df0 = __fsub_rn(cv.x, zv.x); float o0 = __fadd_rn(zv.x, df0);
            float df1 = __fsub_rn(cv.y, zv.y); float o1 = __fadd_rn(zv.y, df1);
            float df2 = __fsub_rn(cv.z, zv.z); float o2 = __fadd_rn(zv.z, df2);
            float df3 = __fsub_rn(cv.w, zv.w); float o3 = __fadd_rn(zv.w, df3);
            lacc += (double)__fmul_rn(df0, df0);
            lacc += (double)__fmul_rn(df1, df1);
            lacc += (double)__fmul_rn(df2, df2);
            lacc += (double)__fmul_rn(df3, df3);
            int kb = sg * 4;
            so[li][lane * 8 + ((kb + 0 + perm) & 7)] = o0;
            so[li][lane * 8 + ((kb + 1 + perm) & 7)] = o1;
            so[li][lane * 8 + ((kb + 2 + perm) & 7)] = o2;
            so[li][lane * 8 + ((kb + 3 + perm) & 7)] = o3;
        }
    }
    __syncthreads();
#pragma unroll 8
    for (int i = 0; i < 32; i++) {
        int d = wid * 32 + i;
        int col = (d & 248) | ((d + (d >> 5)) & 7);
        out[((size_t)b * DD + d) * LL + l0 + lane] = so[lane][col];
    }
#pragma unroll
    for (int o = 16; o > 0; o >>= 1) lacc += __shfl_down_sync(0xffffffffu, lacc, o);
    if (lane == 0) red[wid] = lacc;
    __syncthreads();
    if (wid == 0) {
        double v = (lane < 8) ? red[lane] : 0.0;
#pragma unroll
        for (int o = 4; o > 0; o >>= 1) v += __shfl_down_sync(0xffffffffu, v, o);
        if (lane == 0) atomicAdd(&g_loss, v);
    }
}

__global__ void finalize_kernel(float* __restrict__ out, int out_size) {
    double m = g_loss / (double)NTOT;
    float mf = (float)m;
    float vq = __fadd_rn(__fmul_rn(mf, 0.25f), mf);
    if (out_size > NTOT) out[NTOT] = vq;
}

// ---------------- host ----------------
extern "C" void kernel_launch(void* const* d_in, const int* in_sizes, int n_in,
                              void* d_out, int out_size) {
    const float* z  = (const float*)d_in[0];
    const float* cb = (const float*)d_in[1];
    float* out = (float*)d_out;

    cudaFuncSetAttribute(vq_mma_kernel, cudaFuncAttributeMaxDynamicSharedMemorySize, DYNSMEM);

    zprep_kernel<<<NN / 128, 128>>>(z);
    e2_kernel<<<KK / 8, 256>>>(cb);
    prep_c_kernel<<<KK * DD / 4 / 256, 256>>>(cb);
    dim3 grid(NN / BM, KK / BN);
    vq_mma_kernel<<<grid, 256, DYNSMEM>>>();
    rescue_kernel<<<NN / 8, 256>>>(cb);
    out_loss_kernel<<<NN / 32, 256>>>(cb, out);
    finalize_kernel<<<1, 1>>>(out, out_size);
}

// round 14
// speedup vs baseline: 3.5908x; 1.0471x over previous
#include <cuda_runtime.h>
#include <cuda_fp16.h>
#include <cstdint>

#define NB 16
#define DD 256
#define LL 2048
#define KK 8192
#define NN (NB*LL)        // 32768 z vectors
#define NTOT (NB*DD*LL)
#define BM 256
#define BN 128
#define BKH 64
#define NKITER (DD/BKH)   // 4
#define HSTRIDE 72
#define A_HALFS (BM*HSTRIDE)
#define B_HALFS (BN*HSTRIDE)
#define STAGE_HALFS (A_HALFS+B_HALFS)
#define STAGE_BYTES (STAGE_HALFS*2)       // 55296
#define NSTAGE 3
#define DYNSMEM (NSTAGE*STAGE_BYTES)      // 165888
#define NGRP 1024                         // 8-code groups per n
#define NTILE 64                          // 128-code tiles per n  (= KK/BN)
#define MARGIN_EFF 2.4e-4f                // 2e-4 + fp16 rounding slop
#define EZ_UNSCALE (-0.000244140625f)     // -2 * 2^-13 (exact)
#define OUT_BLOCKS (NN/32)

// ---------------- device scratch ----------------
__device__ __align__(1024) float  g_zT[(size_t)NN*DD];    // 32MB fp32 z [n][d]
__device__ __align__(1024) __half g_zH[(size_t)NN*DD];    // 16MB fp16 z [n][d]
__device__ __align__(1024) __half g_cH[(size_t)KK*DD];    // 4MB fp16 cb*8192
__device__ __align__(1024) __half g_grp16[(size_t)NN*NGRP];// 67MB per-8-group offset minima
__device__ __align__(1024) float  g_tile[(size_t)NN*NTILE];// 8MB per-128-tile offset minima
__device__ float  g_z2[NN];
__device__ float  g_e2[KK];
__device__ int    g_idx[NN];
__device__ double g_loss;
__device__ unsigned g_done;

// ---------------- helpers ----------------
__device__ __forceinline__ uint32_t smem_u32(const void* p) {
    uint32_t a;
    asm("{ .reg .u64 t; cvta.to.shared.u64 t, %1; cvt.u32.u64 %0, t; }" : "=r"(a) : "l"(p));
    return a;
}
#define CP_ASYNC16(sa, gp) \
    asm volatile("cp.async.cg.shared.global [%0], [%1], 16;" :: "r"(sa), "l"(gp) : "memory")
#define CP_COMMIT() asm volatile("cp.async.commit_group;" ::: "memory")
#define CP_WAIT1()  asm volatile("cp.async.wait_group 1;" ::: "memory")
#define CP_WAIT0()  asm volatile("cp.async.wait_group 0;" ::: "memory")

__device__ __forceinline__ void mma_f16(float* c, const uint32_t* a, const uint32_t* b) {
    asm volatile(
        "mma.sync.aligned.m16n8k16.row.col.f32.f16.f16.f32 "
        "{%0,%1,%2,%3}, {%4,%5,%6,%7}, {%8,%9}, {%0,%1,%2,%3};"
        : "+f"(c[0]), "+f"(c[1]), "+f"(c[2]), "+f"(c[3])
        : "r"(a[0]), "r"(a[1]), "r"(a[2]), "r"(a[3]), "r"(b[0]), "r"(b[1]));
}

// ---------------- fused z prep: transpose + fp16 + z2 (exact order) + loss reset ----------------
__global__ __launch_bounds__(128) void zprep_kernel(const float* __restrict__ z) {
    __shared__ float s[64][129];
    const int tid = threadIdx.x;
    const int w = tid >> 5, lane = tid & 31;
    const int n0 = blockIdx.x * 128;
    const int b = n0 >> 11, l0 = n0 & 2047;
    const float* zb = z + (size_t)b * DD * LL + l0;
    if (blockIdx.x == 0 && tid == 0) { g_loss = 0.0; g_done = 0u; }

    float acc = 0.f;
    for (int c = 0; c < 4; c++) {
        __syncthreads();
#pragma unroll
        for (int i = 0; i < 16; i++) {
            int f4 = tid + i * 128;
            int dd = f4 >> 5, l4 = (f4 & 31) << 2;
            float4 v = *reinterpret_cast<const float4*>(&zb[(size_t)(c * 64 + dd) * LL + l4]);
            s[dd][l4] = v.x; s[dd][l4 + 1] = v.y; s[dd][l4 + 2] = v.z; s[dd][l4 + 3] = v.w;
        }
        __syncthreads();
#pragma unroll 16
        for (int dd = 0; dd < 64; dd++) {
            float v = s[dd][tid];
            acc = __fadd_rn(acc, __fmul_rn(v, v));
        }
#pragma unroll 8
        for (int j = 0; j < 32; j++) {
            int row = w + 4 * j;
            float a0 = s[2 * lane][row];
            float a1 = s[2 * lane + 1][row];
            size_t o = (size_t)(n0 + row) * DD + c * 64 + 2 * lane;
            *reinterpret_cast<float2*>(&g_zT[o]) = make_float2(a0, a1);
            *reinterpret_cast<__half2*>(&g_zH[o]) = __floats2half2_rn(a0, a1);
        }
    }
    g_z2[n0 + tid] = acc;
}

// ---------------- fused codebook prep: e2 (validated order) + fp16 scaled copy ----------------
__global__ void cbprep_kernel(const float* __restrict__ cb) {
    int warp = blockIdx.x * 8 + (threadIdx.x >> 5);
    int lane = threadIdx.x & 31;
    const float* r = cb + (size_t)warp * DD;
    float s = 0.f;
#pragma unroll
    for (int i = 0; i < DD / 32; i++) {
        float v = r[lane + i * 32];
        s = fmaf(v, v, s);
        g_cH[(size_t)warp * DD + lane + i * 32] = __float2half_rn(v * 8192.f);
    }
#pragma unroll
    for (int o = 16; o > 0; o >>= 1) s += __shfl_down_sync(0xffffffffu, s, o);
    if (lane == 0) g_e2[warp] = s;
}

// ---------------- main GEMM (R6-proven mainloop; hierarchical fp16 epilogue) ----------------
__device__ __forceinline__ void stage_load(__half* buf, int m0, int n0, int kk0, int tid) {
#pragma unroll
    for (int it = 0; it < 8; it++) {
        int idx = tid + it * 256;
        int row = idx >> 3, ch = (idx & 7) << 3;
        uint32_t sa = smem_u32(buf + row * HSTRIDE + ch);
        CP_ASYNC16(sa, &g_zH[(size_t)(m0 + row) * DD + kk0 + ch]);
    }
#pragma unroll
    for (int it = 0; it < 4; it++) {
        int idx = tid + it * 256;
        int row = idx >> 3, ch = (idx & 7) << 3;
        uint32_t sa = smem_u32(buf + A_HALFS + row * HSTRIDE + ch);
        CP_ASYNC16(sa, &g_cH[(size_t)(n0 + row) * DD + kk0 + ch]);
    }
}

__global__ __launch_bounds__(256, 1) void vq_mma_kernel() {
    extern __shared__ __align__(16) __half hsm[];
    const int tid = threadIdx.x;
    const int wid = tid >> 5, lane = tid & 31;
    const int warpM = wid >> 1, warpN = wid & 1;
    const int q = lane >> 2, r = lane & 3;
    const int m0 = blockIdx.x * BM;
    const int n0 = blockIdx.y * BN;

    float c[4][8][4];
#pragma unroll
    for (int i = 0; i < 4; i++)
#pragma unroll
        for (int j = 0; j < 8; j++)
#pragma unroll
            for (int t = 0; t < 4; t++) c[i][j][t] = 0.f;

    stage_load(hsm, m0, n0, 0, tid); CP_COMMIT();
    stage_load(hsm + STAGE_HALFS, m0, n0, BKH, tid); CP_COMMIT();

    for (int i = 0; i < NKITER; i++) {
        if (i < NKITER - 1) CP_WAIT1(); else CP_WAIT0();
        __syncthreads();
        if (i + 2 < NKITER) {
            stage_load(hsm + ((i + 2) % NSTAGE) * STAGE_HALFS, m0, n0, (i + 2) * BKH, tid);
            CP_COMMIT();
        }
        const __half* As = hsm + (i % NSTAGE) * STAGE_HALFS;
        const __half* Bs = As + A_HALFS;
#pragma unroll
        for (int kb = 0; kb < BKH; kb += 16) {
            uint32_t a[4][4], b[8][2];
#pragma unroll
            for (int mf = 0; mf < 4; mf++) {
                int r0 = warpM * 64 + mf * 16 + q;
                a[mf][0] = *reinterpret_cast<const uint32_t*>(&As[r0 * HSTRIDE + kb + 2 * r]);
                a[mf][1] = *reinterpret_cast<const uint32_t*>(&As[(r0 + 8) * HSTRIDE + kb + 2 * r]);
                a[mf][2] = *reinterpret_cast<const uint32_t*>(&As[r0 * HSTRIDE + kb + 2 * r + 8]);
                a[mf][3] = *reinterpret_cast<const uint32_t*>(&As[(r0 + 8) * HSTRIDE + kb + 2 * r + 8]);
            }
#pragma unroll
            for (int nf = 0; nf < 8; nf++) {
                int cc = warpN * 64 + nf * 8 + q;
                b[nf][0] = *reinterpret_cast<const uint32_t*>(&Bs[cc * HSTRIDE + kb + 2 * r]);
                b[nf][1] = *reinterpret_cast<const uint32_t*>(&Bs[cc * HSTRIDE + kb + 2 * r + 8]);
            }
#pragma unroll
            for (int mf = 0; mf < 4; mf++)
#pragma unroll
                for (int nf = 0; nf < 8; nf++)
                    mma_f16(c[mf][nf], a[mf], b[nf]);
        }
        __syncthreads();
    }

    // ---- epilogue: per-(row, 8-code group) fp16 OFFSET minima (s - z2, Sterbenz-exact) ----
    __half* sgrp = hsm;    // [256 rows][16 halfs], stride 20 halfs
#pragma unroll
    for (int mf = 0; mf < 4; mf++) {
#pragma unroll
        for (int half = 0; half < 2; half++) {
            int lrow = warpM * 64 + mf * 16 + q + half * 8;
            float z2v = g_z2[m0 + lrow];
#pragma unroll
            for (int nf = 0; nf < 8; nf++) {
                int k0 = n0 + warpN * 64 + nf * 8 + 2 * r;
                float e20 = __ldg(&g_e2[k0]);
                float e21 = __ldg(&g_e2[k0 + 1]);
                float s0 = __fadd_rn(__fadd_rn(z2v, e20), c[mf][nf][half * 2 + 0] * EZ_UNSCALE);
                float s1 = __fadd_rn(__fadd_rn(z2v, e21), c[mf][nf][half * 2 + 1] * EZ_UNSCALE);
                float o0 = __fsub_rn(s0, z2v);   // exact (Sterbenz)
                float o1 = __fsub_rn(s1, z2v);
                float best = fminf(o0, o1);
                best = fminf(best, __shfl_xor_sync(0xffffffffu, best, 1));
                best = fminf(best, __shfl_xor_sync(0xffffffffu, best, 2));
                if (r == 0)
                    sgrp[lrow * 20 + warpN * 8 + nf] = __float2half_rn(best);
            }
        }
    }
    __syncthreads();
    {   // thread tid owns row tid: write 16 halfs (32B) + tile min
        const uint2* src = reinterpret_cast<const uint2*>(&sgrp[tid * 20]);
        uint2 u0 = src[0], u1 = src[1], u2 = src[2], u3 = src[3];
        float m = 3.4e38f;
        const __half* hh = &sgrp[tid * 20];
#pragma unroll
        for (int wv = 0; wv < 16; wv++) m = fminf(m, __half2float(hh[wv]));
        __half* dst = g_grp16 + (size_t)(m0 + tid) * NGRP + blockIdx.y * 16;
        uint4 a4 = make_uint4(u0.x, u0.y, u1.x, u1.y);
        uint4 b4 = make_uint4(u2.x, u2.y, u3.x, u3.y);
        reinterpret_cast<uint4*>(dst)[0] = a4;
        reinterpret_cast<uint4*>(dst)[1] = b4;
        g_tile[(size_t)(m0 + tid) * NTILE + blockIdx.y] = m;
    }
}

// ---------------- rescue: hierarchical scan (64 tiles) + exact re-score (bit-exact chain) ----------------
__global__ __launch_bounds__(256) void rescue_kernel(const float* __restrict__ cb) {
    const int lane = threadIdx.x & 31;
    const int n = blockIdx.x * 8 + (threadIdx.x >> 5);
    const float* tptr = g_tile + (size_t)n * NTILE;

    float tm0 = tptr[lane];
    float tm1 = tptr[lane + 32];
    float mn = fminf(tm0, tm1);
#pragma unroll
    for (int off = 16; off > 0; off >>= 1)
        mn = fminf(mn, __shfl_xor_sync(0xffffffffu, mn, off));
    const float T = mn + MARGIN_EFF;

    const float z2v = g_z2[n];
    const float4* zr = reinterpret_cast<const float4*>(g_zT + (size_t)n * DD);
    unsigned long long best = ~0ull;

#pragma unroll
    for (int h = 0; h < 2; h++) {
        float tm = (h == 0) ? tm0 : tm1;
        unsigned tf = __ballot_sync(0xffffffffu, tm <= T);
        while (tf) {
            int t = (__ffs(tf) - 1) + h * 32;
            tf &= tf - 1;
            float go = 3.4e38f;
            if (lane < 16)
                go = __half2float(g_grp16[(size_t)n * NGRP + t * 16 + lane]);
            unsigned gf = __ballot_sync(0xffffffffu, go <= T);
            while (gf) {
                int g = __ffs(gf) - 1;
                gf &= gf - 1;
                unsigned long long p = ~0ull;
                if (lane < 8) {
                    int k = t * 128 + g * 8 + lane;
                    const float4* crow = reinterpret_cast<const float4*>(cb + (size_t)k * DD);
                    float acc = 0.f;
#pragma unroll 8
                    for (int d4 = 0; d4 < DD / 4; d4++) {
                        float4 c4 = __ldg(&crow[d4]);
                        float4 zv = zr[d4];
                        acc = fmaf(zv.x, c4.x, acc);
                        acc = fmaf(zv.y, c4.y, acc);
                        acc = fmaf(zv.z, c4.z, acc);
                        acc = fmaf(zv.w, c4.w, acc);
                    }
                    float s = __fadd_rn(__fadd_rn(z2v, g_e2[k]), -2.0f * acc);
                    p = ((unsigned long long)__float_as_uint(s) << 32) | (unsigned)k;
                }
                if (p < best) best = p;
            }
        }
    }
#pragma unroll
    for (int off = 16; off > 0; off >>= 1) {
        unsigned long long o = __shfl_xor_sync(0xffffffffu, best, off);
        if (o < best) best = o;
    }
    if (lane == 0) g_idx[n] = (int)(best & 0xFFFFFFFFull);
}

// ---------------- output + loss + fused finalize ----------------
__global__ __launch_bounds__(256) void out_loss_kernel(const float* __restrict__ cb,
                                                       float* __restrict__ out, int out_size) {
    __shared__ float so[32][257];
    __shared__ double red[8];
    const int tid = threadIdx.x, wid = tid >> 5, lane = tid & 31;
    const int n0 = blockIdx.x * 32;
    const int b = n0 >> 11, l0 = n0 & 2047;
    double lacc = 0.0;
    const int perm = lane >> 2;

#pragma unroll
    for (int it = 0; it < 4; it++) {
        int li = wid * 4 + it;
        int n = n0 + li;
        int id = g_idx[n];
        const float4* zr = reinterpret_cast<const float4*>(g_zT + (size_t)n * DD);
        const float4* cr = reinterpret_cast<const float4*>(cb + (size_t)id * DD);
#pragma unroll
        for (int sg = 0; sg < 2; sg++) {
            int d4 = lane * 2 + sg;
            float4 zv = zr[d4];
            float4 cv = __ldg(&cr[d4]);
            float df0 = __fsub_rn(cv.x, zv.x); float o0 = __fadd_rn(zv.x, df0);
            float df1 = __fsub_rn(cv.y, zv.y); float o1 = __fadd_rn(zv.y, df1);
            float df2 = __fsub_rn(cv.z, zv.z); float o2 = __fadd_rn(zv.z, df2);
            float df3 = __fsub_rn(cv.w, zv.w); float o3 = __fadd_rn(zv.w, df3);
            lacc += (double)__fmul_rn(df0, df0);
            lacc += (double)__fmul_rn(df1, df1);
            lacc += (double)__fmul_rn(df2, df2);
            lacc += (double)__fmul_rn(df3, df3);
            int kb = sg * 4;
            so[li][lane * 8 + ((kb + 0 + perm) & 7)] = o0;
            so[li][lane * 8 + ((kb + 1 + perm) & 7)] = o1;
            so[li][lane * 8 + ((kb + 2 + perm) & 7)] = o2;
            so[li][lane * 8 + ((kb + 3 + perm) & 7)] = o3;
        }
    }
    __syncthreads();
#pragma unroll 8
    for (int i = 0; i < 32; i++) {
        int d = wid * 32 + i;
        int col = (d & 248) | ((d + (d >> 5)) & 7);
        out[((size_t)b * DD + d) * LL + l0 + lane] = so[lane][col];
    }
#pragma unroll
    for (int o = 16; o > 0; o >>= 1) lacc += __shfl_down_sync(0xffffffffu, lacc, o);
    if (lane == 0) red[wid] = lacc;
    __syncthreads();
    if (wid == 0 && lane == 0) {
        double v = red[0] + red[1] + red[2] + red[3] + red[4] + red[5] + red[6] + red[7];
        atomicAdd(&g_loss, v);
        __threadfence();
        unsigned ticket = atomicAdd(&g_done, 1u);
        if (ticket == OUT_BLOCKS - 1) {       // last block: finalize
            g_done = 0u;                      // reset for next graph replay
            double m = *((volatile double*)&g_loss) / (double)NTOT;
            float mf = (float)m;
            float vq = __fadd_rn(__fmul_rn(mf, 0.25f), mf);
            if (out_size > NTOT) out[NTOT] = vq;
        }
    }
}

// ---------------- host ----------------
extern "C" void kernel_launch(void* const* d_in, const int* in_sizes, int n_in,
                              void* d_out, int out_size) {
    const float* z  = (const float*)d_in[0];
    const float* cb = (const float*)d_in[1];
    float* out = (float*)d_out;

    cudaFuncSetAttribute(vq_mma_kernel, cudaFuncAttributeMaxDynamicSharedMemorySize, DYNSMEM);

    zprep_kernel<<<NN / 128, 128>>>(z);
    cbprep_kernel<<<KK / 8, 256>>>(cb);
    dim3 grid(NN / BM, KK / BN);
    vq_mma_kernel<<<grid, 256, DYNSMEM>>>();
    rescue_kernel<<<NN / 8, 256>>>(cb);
    out_loss_kernel<<<OUT_BLOCKS, 256>>>(cb, out, out_size);
}

// round 15
// speedup vs baseline: 3.6368x; 1.0128x over previous
#include <cuda_runtime.h>
#include <cuda_fp16.h>
#include <cstdint>

#define NB 16
#define DD 256
#define LL 2048
#define KK 8192
#define NN (NB*LL)        // 32768 z vectors
#define NTOT (NB*DD*LL)
#define BM 256
#define BN 128
#define BKH 64
#define NKITER (DD/BKH)   // 4
#define HSTRIDE 72
#define A_HALFS (BM*HSTRIDE)
#define B_HALFS (BN*HSTRIDE)
#define STAGE_HALFS (A_HALFS+B_HALFS)
#define STAGE_BYTES (STAGE_HALFS*2)       // 55296
#define NSTAGE 3
#define DYNSMEM (NSTAGE*STAGE_BYTES)      // 165888
#define NGRP 1024                         // 8-code groups per n
#define NTILE 64                          // 128-code tiles per n  (= KK/BN)
#define MARGIN_EFF 2.4e-4f
#define EZ_UNSCALE (-0.000244140625f)     // -2 * 2^-13 (exact)
#define OUT_BLOCKS (NN/32)
// rescue smem layout (floats, per warp): zrow[256] + cbuf[8][260]
#define RW_FLOATS (256 + 8*260)           // 2336
#define RESCUE_SMEM (8*RW_FLOATS*4)       // 74752 B

// ---------------- device scratch ----------------
__device__ __align__(1024) float  g_zT[(size_t)NN*DD];    // 32MB fp32 z [n][d]
__device__ __align__(1024) __half g_zH[(size_t)NN*DD];    // 16MB fp16 z [n][d]
__device__ __align__(1024) __half g_cH[(size_t)KK*DD];    // 4MB fp16 cb*8192
__device__ __align__(1024) __half g_grp16[(size_t)NN*NGRP];// 67MB per-8-group offset minima
__device__ __align__(1024) float  g_tile[(size_t)NN*NTILE];// 8MB per-128-tile offset minima
__device__ float  g_z2[NN];
__device__ float  g_e2[KK];
__device__ int    g_idx[NN];
__device__ double g_loss;
__device__ unsigned g_done;

// ---------------- helpers ----------------
__device__ __forceinline__ uint32_t smem_u32(const void* p) {
    uint32_t a;
    asm("{ .reg .u64 t; cvta.to.shared.u64 t, %1; cvt.u32.u64 %0, t; }" : "=r"(a) : "l"(p));
    return a;
}
#define CP_ASYNC16(sa, gp) \
    asm volatile("cp.async.cg.shared.global [%0], [%1], 16;" :: "r"(sa), "l"(gp) : "memory")
#define CP_COMMIT() asm volatile("cp.async.commit_group;" ::: "memory")
#define CP_WAIT1()  asm volatile("cp.async.wait_group 1;" ::: "memory")
#define CP_WAIT0()  asm volatile("cp.async.wait_group 0;" ::: "memory")

__device__ __forceinline__ void mma_f16(float* c, const uint32_t* a, const uint32_t* b) {
    asm volatile(
        "mma.sync.aligned.m16n8k16.row.col.f32.f16.f16.f32 "
        "{%0,%1,%2,%3}, {%4,%5,%6,%7}, {%8,%9}, {%0,%1,%2,%3};"
        : "+f"(c[0]), "+f"(c[1]), "+f"(c[2]), "+f"(c[3])
        : "r"(a[0]), "r"(a[1]), "r"(a[2]), "r"(a[3]), "r"(b[0]), "r"(b[1]));
}

// ---------------- fused z prep: transpose + fp16 + z2 (exact order) + loss reset ----------------
__global__ __launch_bounds__(128) void zprep_kernel(const float* __restrict__ z) {
    __shared__ float s[64][129];
    const int tid = threadIdx.x;
    const int w = tid >> 5, lane = tid & 31;
    const int n0 = blockIdx.x * 128;
    const int b = n0 >> 11, l0 = n0 & 2047;
    const float* zb = z + (size_t)b * DD * LL + l0;
    if (blockIdx.x == 0 && tid == 0) { g_loss = 0.0; g_done = 0u; }

    float acc = 0.f;
    for (int c = 0; c < 4; c++) {
        __syncthreads();
#pragma unroll
        for (int i = 0; i < 16; i++) {
            int f4 = tid + i * 128;
            int dd = f4 >> 5, l4 = (f4 & 31) << 2;
            float4 v = *reinterpret_cast<const float4*>(&zb[(size_t)(c * 64 + dd) * LL + l4]);
            s[dd][l4] = v.x; s[dd][l4 + 1] = v.y; s[dd][l4 + 2] = v.z; s[dd][l4 + 3] = v.w;
        }
        __syncthreads();
#pragma unroll 16
        for (int dd = 0; dd < 64; dd++) {
            float v = s[dd][tid];
            acc = __fadd_rn(acc, __fmul_rn(v, v));
        }
#pragma unroll 8
        for (int j = 0; j < 32; j++) {
            int row = w + 4 * j;
            float a0 = s[2 * lane][row];
            float a1 = s[2 * lane + 1][row];
            size_t o = (size_t)(n0 + row) * DD + c * 64 + 2 * lane;
            *reinterpret_cast<float2*>(&g_zT[o]) = make_float2(a0, a1);
            *reinterpret_cast<__half2*>(&g_zH[o]) = __floats2half2_rn(a0, a1);
        }
    }
    g_z2[n0 + tid] = acc;
}

// ---------------- fused codebook prep: e2 (validated order) + fp16 scaled copy ----------------
__global__ void cbprep_kernel(const float* __restrict__ cb) {
    int warp = blockIdx.x * 8 + (threadIdx.x >> 5);
    int lane = threadIdx.x & 31;
    const float* r = cb + (size_t)warp * DD;
    float s = 0.f;
#pragma unroll
    for (int i = 0; i < DD / 32; i++) {
        float v = r[lane + i * 32];
        s = fmaf(v, v, s);
        g_cH[(size_t)warp * DD + lane + i * 32] = __float2half_rn(v * 8192.f);
    }
#pragma unroll
    for (int o = 16; o > 0; o >>= 1) s += __shfl_down_sync(0xffffffffu, s, o);
    if (lane == 0) g_e2[warp] = s;
}

// ---------------- main GEMM (R6-proven mainloop; hierarchical fp16 epilogue) ----------------
__device__ __forceinline__ void stage_load(__half* buf, int m0, int n0, int kk0, int tid) {
#pragma unroll
    for (int it = 0; it < 8; it++) {
        int idx = tid + it * 256;
        int row = idx >> 3, ch = (idx & 7) << 3;
        uint32_t sa = smem_u32(buf + row * HSTRIDE + ch);
        CP_ASYNC16(sa, &g_zH[(size_t)(m0 + row) * DD + kk0 + ch]);
    }
#pragma unroll
    for (int it = 0; it < 4; it++) {
        int idx = tid + it * 256;
        int row = idx >> 3, ch = (idx & 7) << 3;
        uint32_t sa = smem_u32(buf + A_HALFS + row * HSTRIDE + ch);
        CP_ASYNC16(sa, &g_cH[(size_t)(n0 + row) * DD + kk0 + ch]);
    }
}

__global__ __launch_bounds__(256, 1) void vq_mma_kernel() {
    extern __shared__ __align__(16) __half hsm[];
    const int tid = threadIdx.x;
    const int wid = tid >> 5, lane = tid & 31;
    const int warpM = wid >> 1, warpN = wid & 1;
    const int q = lane >> 2, r = lane & 3;
    const int m0 = blockIdx.x * BM;
    const int n0 = blockIdx.y * BN;

    float c[4][8][4];
#pragma unroll
    for (int i = 0; i < 4; i++)
#pragma unroll
        for (int j = 0; j < 8; j++)
#pragma unroll
            for (int t = 0; t < 4; t++) c[i][j][t] = 0.f;

    stage_load(hsm, m0, n0, 0, tid); CP_COMMIT();
    stage_load(hsm + STAGE_HALFS, m0, n0, BKH, tid); CP_COMMIT();

    for (int i = 0; i < NKITER; i++) {
        if (i < NKITER - 1) CP_WAIT1(); else CP_WAIT0();
        __syncthreads();
        if (i + 2 < NKITER) {
            stage_load(hsm + ((i + 2) % NSTAGE) * STAGE_HALFS, m0, n0, (i + 2) * BKH, tid);
            CP_COMMIT();
        }
        const __half* As = hsm + (i % NSTAGE) * STAGE_HALFS;
        const __half* Bs = As + A_HALFS;
#pragma unroll
        for (int kb = 0; kb < BKH; kb += 16) {
            uint32_t a[4][4], b[8][2];
#pragma unroll
            for (int mf = 0; mf < 4; mf++) {
                int r0 = warpM * 64 + mf * 16 + q;
                a[mf][0] = *reinterpret_cast<const uint32_t*>(&As[r0 * HSTRIDE + kb + 2 * r]);
                a[mf][1] = *reinterpret_cast<const uint32_t*>(&As[(r0 + 8) * HSTRIDE + kb + 2 * r]);
                a[mf][2] = *reinterpret_cast<const uint32_t*>(&As[r0 * HSTRIDE + kb + 2 * r + 8]);
                a[mf][3] = *reinterpret_cast<const uint32_t*>(&As[(r0 + 8) * HSTRIDE + kb + 2 * r + 8]);
            }
#pragma unroll
            for (int nf = 0; nf < 8; nf++) {
                int cc = warpN * 64 + nf * 8 + q;
                b[nf][0] = *reinterpret_cast<const uint32_t*>(&Bs[cc * HSTRIDE + kb + 2 * r]);
                b[nf][1] = *reinterpret_cast<const uint32_t*>(&Bs[cc * HSTRIDE + kb + 2 * r + 8]);
            }
#pragma unroll
            for (int mf = 0; mf < 4; mf++)
#pragma unroll
                for (int nf = 0; nf < 8; nf++)
                    mma_f16(c[mf][nf], a[mf], b[nf]);
        }
        __syncthreads();
    }

    // ---- epilogue: per-(row, 8-code group) fp16 OFFSET minima (s - z2, Sterbenz-exact) ----
    __half* sgrp = hsm;    // [256 rows][16 halfs], stride 20 halfs
#pragma unroll
    for (int mf = 0; mf < 4; mf++) {
#pragma unroll
        for (int half = 0; half < 2; half++) {
            int lrow = warpM * 64 + mf * 16 + q + half * 8;
            float z2v = g_z2[m0 + lrow];
#pragma unroll
            for (int nf = 0; nf < 8; nf++) {
                int k0 = n0 + warpN * 64 + nf * 8 + 2 * r;
                float e20 = __ldg(&g_e2[k0]);
                float e21 = __ldg(&g_e2[k0 + 1]);
                float s0 = __fadd_rn(__fadd_rn(z2v, e20), c[mf][nf][half * 2 + 0] * EZ_UNSCALE);
                float s1 = __fadd_rn(__fadd_rn(z2v, e21), c[mf][nf][half * 2 + 1] * EZ_UNSCALE);
                float o0 = __fsub_rn(s0, z2v);   // exact (Sterbenz)
                float o1 = __fsub_rn(s1, z2v);
                float best = fminf(o0, o1);
                best = fminf(best, __shfl_xor_sync(0xffffffffu, best, 1));
                best = fminf(best, __shfl_xor_sync(0xffffffffu, best, 2));
                if (r == 0)
                    sgrp[lrow * 20 + warpN * 8 + nf] = __float2half_rn(best);
            }
        }
    }
    __syncthreads();
    {
        const uint2* src = reinterpret_cast<const uint2*>(&sgrp[tid * 20]);
        uint2 u0 = src[0], u1 = src[1], u2 = src[2], u3 = src[3];
        float m = 3.4e38f;
        const __half* hh = &sgrp[tid * 20];
#pragma unroll
        for (int wv = 0; wv < 16; wv++) m = fminf(m, __half2float(hh[wv]));
        __half* dst = g_grp16 + (size_t)(m0 + tid) * NGRP + blockIdx.y * 16;
        reinterpret_cast<uint4*>(dst)[0] = make_uint4(u0.x, u0.y, u1.x, u1.y);
        reinterpret_cast<uint4*>(dst)[1] = make_uint4(u2.x, u2.y, u3.x, u3.y);
        g_tile[(size_t)(m0 + tid) * NTILE + blockIdx.y] = m;
    }
}

// ---------------- rescue: hierarchical scan + smem-staged exact re-score ----------------
__global__ __launch_bounds__(256) void rescue_kernel(const float* __restrict__ cb) {
    extern __shared__ __align__(16) float rsm[];
    const int lane = threadIdx.x & 31;
    const int w = threadIdx.x >> 5;
    const int n = blockIdx.x * 8 + w;
    float* zrow = rsm + w * RW_FLOATS;          // [256]
    float* cbuf = zrow + 256;                   // [8][260]

    // stage z row once (2 float4 per lane, coalesced)
    {
        const float4* zg = reinterpret_cast<const float4*>(g_zT + (size_t)n * DD);
        reinterpret_cast<float4*>(zrow)[lane]      = zg[lane];
        reinterpret_cast<float4*>(zrow)[lane + 32] = zg[lane + 32];
    }

    const float* tptr = g_tile + (size_t)n * NTILE;
    float tm0 = tptr[lane];
    float tm1 = tptr[lane + 32];
    float mn = fminf(tm0, tm1);
#pragma unroll
    for (int off = 16; off > 0; off >>= 1)
        mn = fminf(mn, __shfl_xor_sync(0xffffffffu, mn, off));
    const float T = mn + MARGIN_EFF;

    const float z2v = g_z2[n];
    unsigned long long best = ~0ull;
    __syncwarp();

#pragma unroll
    for (int h = 0; h < 2; h++) {
        float tm = (h == 0) ? tm0 : tm1;
        unsigned tf = __ballot_sync(0xffffffffu, tm <= T);
        while (tf) {
            int t = (__ffs(tf) - 1) + h * 32;
            tf &= tf - 1;
            float go = 3.4e38f;
            if (lane < 16)
                go = __half2float(g_grp16[(size_t)n * NGRP + t * 16 + lane]);
            unsigned gf = __ballot_sync(0xffffffffu, go <= T);
            while (gf) {
                int g = __ffs(gf) - 1;
                gf &= gf - 1;
                int k0 = t * 128 + g * 8;
                // cooperative stage of 8 rows (1KB each) with MLP 16/lane
                {
                    const float4* gr = reinterpret_cast<const float4*>(
                        cb + (size_t)(k0 + (lane >> 2)) * DD);
                    float* dst = cbuf + (lane >> 2) * 260;
                    int q0 = lane & 3;
#pragma unroll
                    for (int i = 0; i < 16; i++) {
                        int c4i = q0 + 4 * i;
                        *reinterpret_cast<float4*>(&dst[c4i * 4]) = __ldg(&gr[c4i]);
                    }
                }
                __syncwarp();
                unsigned long long p = ~0ull;
                if (lane < 8) {
                    int k = k0 + lane;
                    const float* cr = cbuf + lane * 260;
                    float acc = 0.f;
#pragma unroll 8
                    for (int d4 = 0; d4 < DD / 4; d4++) {
                        float4 c4 = *reinterpret_cast<const float4*>(&cr[d4 * 4]);
                        float4 zv = *reinterpret_cast<const float4*>(&zrow[d4 * 4]);
                        acc = fmaf(zv.x, c4.x, acc);
                        acc = fmaf(zv.y, c4.y, acc);
                        acc = fmaf(zv.z, c4.z, acc);
                        acc = fmaf(zv.w, c4.w, acc);
                    }
                    float s = __fadd_rn(__fadd_rn(z2v, g_e2[k]), -2.0f * acc);
                    p = ((unsigned long long)__float_as_uint(s) << 32) | (unsigned)k;
                }
                __syncwarp();
                if (p < best) best = p;
            }
        }
    }
#pragma unroll
    for (int off = 16; off > 0; off >>= 1) {
        unsigned long long o = __shfl_xor_sync(0xffffffffu, best, off);
        if (o < best) best = o;
    }
    if (lane == 0) g_idx[n] = (int)(best & 0xFFFFFFFFull);
}

// ---------------- output + loss + fused finalize ----------------
__global__ __launch_bounds__(256) void out_loss_kernel(const float* __restrict__ cb,
                                                       float* __restrict__ out, int out_size) {
    __shared__ float so[32][257];
    __shared__ double red[8];
    const int tid = threadIdx.x, wid = tid >> 5, lane = tid & 31;
    const int n0 = blockIdx.x * 32;
    const int b = n0 >> 11, l0 = n0 & 2047;
    double lacc = 0.0;
    const int perm = lane >> 2;

#pragma unroll
    for (int it = 0; it < 4; it++) {
        int li = wid * 4 + it;
        int n = n0 + li;
        int id = g_idx[n];
        const float4* zr = reinterpret_cast<const float4*>(g_zT + (size_t)n * DD);
        const float4* cr = reinterpret_cast<const float4*>(cb + (size_t)id * DD);
#pragma unroll
        for (int sg = 0; sg < 2; sg++) {
            int d4 = lane * 2 + sg;
            float4 zv = zr[d4];
            float4 cv = __ldg(&cr[d4]);
            float df0 = __fsub_rn(cv.x, zv.x); float o0 = __fadd_rn(zv.x, df0);
            float df1 = __fsub_rn(cv.y, zv.y); float o1 = __fadd_rn(zv.y, df1);
            float df2 = __fsub_rn(cv.z, zv.z); float o2 = __fadd_rn(zv.z, df2);
            float df3 = __fsub_rn(cv.w, zv.w); float o3 = __fadd_rn(zv.w, df3);
            lacc += (double)__fmul_rn(df0, df0);
            lacc += (double)__fmul_rn(df1, df1);
            lacc += (double)__fmul_rn(df2, df2);
            lacc += (double)__fmul_rn(df3, df3);
            int kb = sg * 4;
            so[li][lane * 8 + ((kb + 0 + perm) & 7)] = o0;
            so[li][lane * 8 + ((kb + 1 + perm) & 7)] = o1;
            so[li][lane * 8 + ((kb + 2 + perm) & 7)] = o2;
            so[li][lane * 8 + ((kb + 3 + perm) & 7)] = o3;
        }
    }
    __syncthreads();
#pragma unroll 8
    for (int i = 0; i < 32; i++) {
        int d = wid * 32 + i;
        int col = (d & 248) | ((d + (d >> 5)) & 7);
        out[((size_t)b * DD + d) * LL + l0 + lane] = so[lane][col];
    }
#pragma unroll
    for (int o = 16; o > 0; o >>= 1) lacc += __shfl_down_sync(0xffffffffu, lacc, o);
    if (lane == 0) red[wid] = lacc;
    __syncthreads();
    if (wid == 0 && lane == 0) {
        double v = red[0] + red[1] + red[2] + red[3] + red[4] + red[5] + red[6] + red[7];
        atomicAdd(&g_loss, v);
        __threadfence();
        unsigned ticket = atomicAdd(&g_done, 1u);
        if (ticket == OUT_BLOCKS - 1) {
            g_done = 0u;
            double m = *((volatile double*)&g_loss) / (double)NTOT;
            float mf = (float)m;
            float vq = __fadd_rn(__fmul_rn(mf, 0.25f), mf);
            if (out_size > NTOT) out[NTOT] = vq;
        }
    }
}

// ---------------- host ----------------
extern "C" void kernel_launch(void* const* d_in, const int* in_sizes, int n_in,
                              void* d_out, int out_size) {
    const float* z  = (const float*)d_in[0];
    const float* cb = (const float*)d_in[1];
    float* out = (float*)d_out;

    cudaFuncSetAttribute(vq_mma_kernel, cudaFuncAttributeMaxDynamicSharedMemorySize, DYNSMEM);
    cudaFuncSetAttribute(rescue_kernel, cudaFuncAttributeMaxDynamicSharedMemorySize, RESCUE_SMEM);

    zprep_kernel<<<NN / 128, 128>>>(z);
    cbprep_kernel<<<KK / 8, 256>>>(cb);
    dim3 grid(NN / BM, KK / BN);
    vq_mma_kernel<<<grid, 256, DYNSMEM>>>();
    rescue_kernel<<<NN / 8, 256, RESCUE_SMEM>>>(cb);
    out_loss_kernel<<<OUT_BLOCKS, 256>>>(cb, out, out_size);
}

// round 16
// speedup vs baseline: 3.7078x; 1.0195x over previous
#include <cuda_runtime.h>
#include <cuda_fp16.h>
#include <cstdint>

#define NB 16
#define DD 256
#define LL 2048
#define KK 8192
#define NN (NB*LL)        // 32768 z vectors
#define NTOT (NB*DD*LL)
#define BM 256
#define BN 128
#define BKH 64
#define NKITER (DD/BKH)   // 4
#define HSTRIDE 72
#define A_HALFS (BM*HSTRIDE)
#define B_HALFS (BN*HSTRIDE)
#define STAGE_HALFS (A_HALFS+B_HALFS)
#define STAGE_BYTES (STAGE_HALFS*2)       // 55296
#define NSTAGE 3
#define DYNSMEM (NSTAGE*STAGE_BYTES)      // 165888
#define NGRP 1024                         // 8-code groups per n
#define NTILE 64                          // 128-code tiles per n  (= KK/BN)
#define MARGIN_EFF 2.4e-4f
#define EZ_UNSCALE (-0.000244140625f)     // -2 * 2^-13 (exact)
#define OUT_BLOCKS (NN/32)
// rescue smem (floats, per warp): zrow[256] + cbuf[8][260]
#define RW_FLOATS (256 + 8*260)           // 2336
#define RESCUE_WARPS 4
#define RESCUE_SMEM (RESCUE_WARPS*RW_FLOATS*4)   // 37376 B

// ---------------- device scratch ----------------
__device__ __align__(1024) float  g_zT[(size_t)NN*DD];    // 32MB fp32 z [n][d]
__device__ __align__(1024) __half g_zH[(size_t)NN*DD];    // 16MB fp16 z [n][d]
__device__ __align__(1024) __half g_cH[(size_t)KK*DD];    // 4MB fp16 cb*8192
__device__ __align__(1024) __half g_grp16[(size_t)NN*NGRP];// 67MB per-8-group offset minima
__device__ __align__(1024) float  g_tile[(size_t)NN*NTILE];// 8MB per-128-tile offset minima
__device__ float  g_z2[NN];
__device__ float  g_e2[KK];
__device__ int    g_idx[NN];
__device__ double g_loss;
__device__ unsigned g_done;

// ---------------- helpers ----------------
__device__ __forceinline__ uint32_t smem_u32(const void* p) {
    uint32_t a;
    asm("{ .reg .u64 t; cvta.to.shared.u64 t, %1; cvt.u32.u64 %0, t; }" : "=r"(a) : "l"(p));
    return a;
}
#define CP_ASYNC16(sa, gp) \
    asm volatile("cp.async.cg.shared.global [%0], [%1], 16;" :: "r"(sa), "l"(gp) : "memory")
#define CP_COMMIT() asm volatile("cp.async.commit_group;" ::: "memory")
#define CP_WAIT1()  asm volatile("cp.async.wait_group 1;" ::: "memory")
#define CP_WAIT0()  asm volatile("cp.async.wait_group 0;" ::: "memory")

__device__ __forceinline__ void mma_f16(float* c, const uint32_t* a, const uint32_t* b) {
    asm volatile(
        "mma.sync.aligned.m16n8k16.row.col.f32.f16.f16.f32 "
        "{%0,%1,%2,%3}, {%4,%5,%6,%7}, {%8,%9}, {%0,%1,%2,%3};"
        : "+f"(c[0]), "+f"(c[1]), "+f"(c[2]), "+f"(c[3])
        : "r"(a[0]), "r"(a[1]), "r"(a[2]), "r"(a[3]), "r"(b[0]), "r"(b[1]));
}

// ---------------- fused z prep: transpose + fp16 + z2 (exact order) + loss reset ----------------
__global__ __launch_bounds__(128) void zprep_kernel(const float* __restrict__ z) {
    __shared__ float s[64][129];
    const int tid = threadIdx.x;
    const int w = tid >> 5, lane = tid & 31;
    const int n0 = blockIdx.x * 128;
    const int b = n0 >> 11, l0 = n0 & 2047;
    const float* zb = z + (size_t)b * DD * LL + l0;
    if (blockIdx.x == 0 && tid == 0) { g_loss = 0.0; g_done = 0u; }

    float acc = 0.f;
    for (int c = 0; c < 4; c++) {
        __syncthreads();
#pragma unroll
        for (int i = 0; i < 16; i++) {
            int f4 = tid + i * 128;
            int dd = f4 >> 5, l4 = (f4 & 31) << 2;
            float4 v = *reinterpret_cast<const float4*>(&zb[(size_t)(c * 64 + dd) * LL + l4]);
            s[dd][l4] = v.x; s[dd][l4 + 1] = v.y; s[dd][l4 + 2] = v.z; s[dd][l4 + 3] = v.w;
        }
        __syncthreads();
#pragma unroll 16
        for (int dd = 0; dd < 64; dd++) {
            float v = s[dd][tid];
            acc = __fadd_rn(acc, __fmul_rn(v, v));
        }
#pragma unroll 8
        for (int j = 0; j < 32; j++) {
            int row = w + 4 * j;
            float a0 = s[2 * lane][row];
            float a1 = s[2 * lane + 1][row];
            size_t o = (size_t)(n0 + row) * DD + c * 64 + 2 * lane;
            *reinterpret_cast<float2*>(&g_zT[o]) = make_float2(a0, a1);
            *reinterpret_cast<__half2*>(&g_zH[o]) = __floats2half2_rn(a0, a1);
        }
    }
    g_z2[n0 + tid] = acc;
}

// ---------------- fused codebook prep: e2 (validated order) + fp16 scaled copy ----------------
__global__ void cbprep_kernel(const float* __restrict__ cb) {
    int warp = blockIdx.x * 8 + (threadIdx.x >> 5);
    int lane = threadIdx.x & 31;
    const float* r = cb + (size_t)warp * DD;
    float s = 0.f;
#pragma unroll
    for (int i = 0; i < DD / 32; i++) {
        float v = r[lane + i * 32];
        s = fmaf(v, v, s);
        g_cH[(size_t)warp * DD + lane + i * 32] = __float2half_rn(v * 8192.f);
    }
#pragma unroll
    for (int o = 16; o > 0; o >>= 1) s += __shfl_down_sync(0xffffffffu, s, o);
    if (lane == 0) g_e2[warp] = s;
}

// ---------------- main GEMM (R6-proven mainloop; hierarchical fp16 epilogue) ----------------
__device__ __forceinline__ void stage_load(__half* buf, int m0, int n0, int kk0, int tid) {
#pragma unroll
    for (int it = 0; it < 8; it++) {
        int idx = tid + it * 256;
        int row = idx >> 3, ch = (idx & 7) << 3;
        uint32_t sa = smem_u32(buf + row * HSTRIDE + ch);
        CP_ASYNC16(sa, &g_zH[(size_t)(m0 + row) * DD + kk0 + ch]);
    }
#pragma unroll
    for (int it = 0; it < 4; it++) {
        int idx = tid + it * 256;
        int row = idx >> 3, ch = (idx & 7) << 3;
        uint32_t sa = smem_u32(buf + A_HALFS + row * HSTRIDE + ch);
        CP_ASYNC16(sa, &g_cH[(size_t)(n0 + row) * DD + kk0 + ch]);
    }
}

__global__ __launch_bounds__(256, 1) void vq_mma_kernel() {
    extern __shared__ __align__(16) __half hsm[];
    const int tid = threadIdx.x;
    const int wid = tid >> 5, lane = tid & 31;
    const int warpM = wid >> 1, warpN = wid & 1;
    const int q = lane >> 2, r = lane & 3;
    const int m0 = blockIdx.x * BM;
    const int n0 = blockIdx.y * BN;

    float c[4][8][4];
#pragma unroll
    for (int i = 0; i < 4; i++)
#pragma unroll
        for (int j = 0; j < 8; j++)
#pragma unroll
            for (int t = 0; t < 4; t++) c[i][j][t] = 0.f;

    stage_load(hsm, m0, n0, 0, tid); CP_COMMIT();
    stage_load(hsm + STAGE_HALFS, m0, n0, BKH, tid); CP_COMMIT();

    for (int i = 0; i < NKITER; i++) {
        if (i < NKITER - 1) CP_WAIT1(); else CP_WAIT0();
        __syncthreads();
        if (i + 2 < NKITER) {
            stage_load(hsm + ((i + 2) % NSTAGE) * STAGE_HALFS, m0, n0, (i + 2) * BKH, tid);
            CP_COMMIT();
        }
        const __half* As = hsm + (i % NSTAGE) * STAGE_HALFS;
        const __half* Bs = As + A_HALFS;
#pragma unroll
        for (int kb = 0; kb < BKH; kb += 16) {
            uint32_t a[4][4], b[8][2];
#pragma unroll
            for (int mf = 0; mf < 4; mf++) {
                int r0 = warpM * 64 + mf * 16 + q;
                a[mf][0] = *reinterpret_cast<const uint32_t*>(&As[r0 * HSTRIDE + kb + 2 * r]);
                a[mf][1] = *reinterpret_cast<const uint32_t*>(&As[(r0 + 8) * HSTRIDE + kb + 2 * r]);
                a[mf][2] = *reinterpret_cast<const uint32_t*>(&As[r0 * HSTRIDE + kb + 2 * r + 8]);
                a[mf][3] = *reinterpret_cast<const uint32_t*>(&As[(r0 + 8) * HSTRIDE + kb + 2 * r + 8]);
            }
#pragma unroll
            for (int nf = 0; nf < 8; nf++) {
                int cc = warpN * 64 + nf * 8 + q;
                b[nf][0] = *reinterpret_cast<const uint32_t*>(&Bs[cc * HSTRIDE + kb + 2 * r]);
                b[nf][1] = *reinterpret_cast<const uint32_t*>(&Bs[cc * HSTRIDE + kb + 2 * r + 8]);
            }
#pragma unroll
            for (int mf = 0; mf < 4; mf++)
#pragma unroll
                for (int nf = 0; nf < 8; nf++)
                    mma_f16(c[mf][nf], a[mf], b[nf]);
        }
        __syncthreads();
    }

    // ---- epilogue: per-(row, 8-code group) fp16 OFFSET minima (s - z2, Sterbenz-exact) ----
    __half* sgrp = hsm;    // [256 rows][16 halfs], stride 20 halfs
#pragma unroll
    for (int mf = 0; mf < 4; mf++) {
#pragma unroll
        for (int half = 0; half < 2; half++) {
            int lrow = warpM * 64 + mf * 16 + q + half * 8;
            float z2v = g_z2[m0 + lrow];
#pragma unroll
            for (int nf = 0; nf < 8; nf++) {
                int k0 = n0 + warpN * 64 + nf * 8 + 2 * r;
                float e20 = __ldg(&g_e2[k0]);
                float e21 = __ldg(&g_e2[k0 + 1]);
                float s0 = __fadd_rn(__fadd_rn(z2v, e20), c[mf][nf][half * 2 + 0] * EZ_UNSCALE);
                float s1 = __fadd_rn(__fadd_rn(z2v, e21), c[mf][nf][half * 2 + 1] * EZ_UNSCALE);
                float o0 = __fsub_rn(s0, z2v);   // exact (Sterbenz)
                float o1 = __fsub_rn(s1, z2v);
                float best = fminf(o0, o1);
                best = fminf(best, __shfl_xor_sync(0xffffffffu, best, 1));
                best = fminf(best, __shfl_xor_sync(0xffffffffu, best, 2));
                if (r == 0)
                    sgrp[lrow * 20 + warpN * 8 + nf] = __float2half_rn(best);
            }
        }
    }
    __syncthreads();
    {
        const uint2* src = reinterpret_cast<const uint2*>(&sgrp[tid * 20]);
        uint2 u0 = src[0], u1 = src[1], u2 = src[2], u3 = src[3];
        float m = 3.4e38f;
        const __half* hh = &sgrp[tid * 20];
#pragma unroll
        for (int wv = 0; wv < 16; wv++) m = fminf(m, __half2float(hh[wv]));
        __half* dst = g_grp16 + (size_t)(m0 + tid) * NGRP + blockIdx.y * 16;
        reinterpret_cast<uint4*>(dst)[0] = make_uint4(u0.x, u0.y, u1.x, u1.y);
        reinterpret_cast<uint4*>(dst)[1] = make_uint4(u2.x, u2.y, u3.x, u3.y);
        g_tile[(size_t)(m0 + tid) * NTILE + blockIdx.y] = m;
    }
}

// ---------------- rescue: hierarchical scan + smem-staged exact re-score (4-warp blocks) ----------------
__global__ __launch_bounds__(RESCUE_WARPS*32) void rescue_kernel(const float* __restrict__ cb) {
    extern __shared__ __align__(16) float rsm[];
    const int lane = threadIdx.x & 31;
    const int w = threadIdx.x >> 5;
    const int n = blockIdx.x * RESCUE_WARPS + w;
    float* zrow = rsm + w * RW_FLOATS;          // [256]
    float* cbuf = zrow + 256;                   // [8][260]

    // stage z row once (2 float4 per lane, coalesced)
    {
        const float4* zg = reinterpret_cast<const float4*>(g_zT + (size_t)n * DD);
        reinterpret_cast<float4*>(zrow)[lane]      = zg[lane];
        reinterpret_cast<float4*>(zrow)[lane + 32] = zg[lane + 32];
    }

    const float* tptr = g_tile + (size_t)n * NTILE;
    float tm0 = tptr[lane];
    float tm1 = tptr[lane + 32];
    float mn = fminf(tm0, tm1);
#pragma unroll
    for (int off = 16; off > 0; off >>= 1)
        mn = fminf(mn, __shfl_xor_sync(0xffffffffu, mn, off));
    const float T = mn + MARGIN_EFF;

    const float z2v = g_z2[n];
    unsigned long long best = ~0ull;
    __syncwarp();

#pragma unroll
    for (int h = 0; h < 2; h++) {
        float tm = (h == 0) ? tm0 : tm1;
        unsigned tf = __ballot_sync(0xffffffffu, tm <= T);
        while (tf) {
            int t = (__ffs(tf) - 1) + h * 32;
            tf &= tf - 1;
            float go = 3.4e38f;
            if (lane < 16)
                go = __half2float(g_grp16[(size_t)n * NGRP + t * 16 + lane]);
            unsigned gf = __ballot_sync(0xffffffffu, go <= T);
            while (gf) {
                int g = __ffs(gf) - 1;
                gf &= gf - 1;
                int k0 = t * 128 + g * 8;
                // cooperative stage of 8 rows (1KB each)
                {
                    const float4* gr = reinterpret_cast<const float4*>(
                        cb + (size_t)(k0 + (lane >> 2)) * DD);
                    float* dst = cbuf + (lane >> 2) * 260;
                    int q0 = lane & 3;
#pragma unroll
                    for (int i = 0; i < 16; i++) {
                        int c4i = q0 + 4 * i;
                        *reinterpret_cast<float4*>(&dst[c4i * 4]) = __ldg(&gr[c4i]);
                    }
                }
                __syncwarp();
                unsigned long long p = ~0ull;
                if (lane < 8) {
                    int k = k0 + lane;
                    const float* cr = cbuf + lane * 260;
                    float acc = 0.f;
#pragma unroll 8
                    for (int d4 = 0; d4 < DD / 4; d4++) {
                        float4 c4 = *reinterpret_cast<const float4*>(&cr[d4 * 4]);
                        float4 zv = *reinterpret_cast<const float4*>(&zrow[d4 * 4]);
                        acc = fmaf(zv.x, c4.x, acc);
                        acc = fmaf(zv.y, c4.y, acc);
                        acc = fmaf(zv.z, c4.z, acc);
                        acc = fmaf(zv.w, c4.w, acc);
                    }
                    float s = __fadd_rn(__fadd_rn(z2v, g_e2[k]), -2.0f * acc);
                    p = ((unsigned long long)__float_as_uint(s) << 32) | (unsigned)k;
                }
                __syncwarp();
                if (p < best) best = p;
            }
        }
    }
#pragma unroll
    for (int off = 16; off > 0; off >>= 1) {
        unsigned long long o = __shfl_xor_sync(0xffffffffu, best, off);
        if (o < best) best = o;
    }
    if (lane == 0) g_idx[n] = (int)(best & 0xFFFFFFFFull);
}

// ---------------- output + loss + fused finalize ----------------
__global__ __launch_bounds__(256) void out_loss_kernel(const float* __restrict__ cb,
                                                       float* __restrict__ out, int out_size) {
    __shared__ float so[32][257];
    __shared__ double red[8];
    const int tid = threadIdx.x, wid = tid >> 5, lane = tid & 31;
    const int n0 = blockIdx.x * 32;
    const int b = n0 >> 11, l0 = n0 & 2047;
    double lacc = 0.0;
    const int perm = lane >> 2;

#pragma unroll
    for (int it = 0; it < 4; it++) {
        int li = wid * 4 + it;
        int n = n0 + li;
        int id = g_idx[n];
        const float4* zr = reinterpret_cast<const float4*>(g_zT + (size_t)n * DD);
        const float4* cr = reinterpret_cast<const float4*>(cb + (size_t)id * DD);
#pragma unroll
        for (int sg = 0; sg < 2; sg++) {
            int d4 = lane * 2 + sg;
            float4 zv = zr[d4];
            float4 cv = __ldg(&cr[d4]);
            float df0 = __fsub_rn(cv.x, zv.x); float o0 = __fadd_rn(zv.x, df0);
            float df1 = __fsub_rn(cv.y, zv.y); float o1 = __fadd_rn(zv.y, df1);
            float df2 = __fsub_rn(cv.z, zv.z); float o2 = __fadd_rn(zv.z, df2);
            float df3 = __fsub_rn(cv.w, zv.w); float o3 = __fadd_rn(zv.w, df3);
            lacc += (double)__fmul_rn(df0, df0);
            lacc += (double)__fmul_rn(df1, df1);
            lacc += (double)__fmul_rn(df2, df2);
            lacc += (double)__fmul_rn(df3, df3);
            int kb = sg * 4;
            so[li][lane * 8 + ((kb + 0 + perm) & 7)] = o0;
            so[li][lane * 8 + ((kb + 1 + perm) & 7)] = o1;
            so[li][lane * 8 + ((kb + 2 + perm) & 7)] = o2;
            so[li][lane * 8 + ((kb + 3 + perm) & 7)] = o3;
        }
    }
    __syncthreads();
#pragma unroll 8
    for (int i = 0; i < 32; i++) {
        int d = wid * 32 + i;
        int col = (d & 248) | ((d + (d >> 5)) & 7);
        out[((size_t)b * DD + d) * LL + l0 + lane] = so[lane][col];
    }
#pragma unroll
    for (int o = 16; o > 0; o >>= 1) lacc += __shfl_down_sync(0xffffffffu, lacc, o);
    if (lane == 0) red[wid] = lacc;
    __syncthreads();
    if (wid == 0 && lane == 0) {
        double v = red[0] + red[1] + red[2] + red[3] + red[4] + red[5] + red[6] + red[7];
        atomicAdd(&g_loss, v);
        __threadfence();
        unsigned ticket = atomicAdd(&g_done, 1u);
        if (ticket == OUT_BLOCKS - 1) {
            g_done = 0u;
            double m = *((volatile double*)&g_loss) / (double)NTOT;
            float mf = (float)m;
            float vq = __fadd_rn(__fmul_rn(mf, 0.25f), mf);
            if (out_size > NTOT) out[NTOT] = vq;
        }
    }
}

// ---------------- host ----------------
extern "C" void kernel_launch(void* const* d_in, const int* in_sizes, int n_in,
                              void* d_out, int out_size) {
    const float* z  = (const float*)d_in[0];
    const float* cb = (const float*)d_in[1];
    float* out = (float*)d_out;

    cudaFuncSetAttribute(vq_mma_kernel, cudaFuncAttributeMaxDynamicSharedMemorySize, DYNSMEM);
    cudaFuncSetAttribute(rescue_kernel, cudaFuncAttributeMaxDynamicSharedMemorySize, RESCUE_SMEM);

    zprep_kernel<<<NN / 128, 128>>>(z);
    cbprep_kernel<<<KK / 8, 256>>>(cb);
    dim3 grid(NN / BM, KK / BN);
    vq_mma_kernel<<<grid, 256, DYNSMEM>>>();
    rescue_kernel<<<NN / RESCUE_WARPS, RESCUE_WARPS * 32, RESCUE_SMEM>>>(cb);
    out_loss_kernel<<<OUT_BLOCKS, 256>>>(cb, out, out_size);
}